// round 1
// baseline (speedup 1.0000x reference)
#include <cuda_runtime.h>
#include <math.h>

#define DIMC   256
#define HEADS  8
#define DHEAD  32
#define WSZ    8
#define SHIFTW 4
#define IMGH   64
#define IMGW   64
#define BATCH  16
#define NTOK   64                    // tokens per window
#define NWIN   64                    // windows per image
#define MTOK   (BATCH*IMGH*IMGW)     // 65536 tokens
#define QSCALE 0.17677669529663687f  // 32^-0.5

// -------- scratch (device globals; allocation-free at launch time) --------
__device__ float g_x0w[MTOK*DIMC];   // LN+shift+partition of x0 (kv source)
__device__ float g_x1w[MTOK*DIMC];   // LN+shift+partition of x1 (q source)
__device__ float g_q  [MTOK*DIMC];   // (win, head, n, d)
__device__ float g_k  [MTOK*DIMC];
__device__ float g_v  [MTOK*DIMC];
__device__ float g_ao [MTOK*DIMC];   // attention out, (win, n, dim)
__device__ float g_x  [MTOK*DIMC];   // residual stream after attention
__device__ float g_xln[MTOK*DIMC];   // LN2(x)
__device__ float g_h  [MTOK*4*DIMC]; // FC1 activations

// -------------------------- block reduce helper ---------------------------
__device__ __forceinline__ float block_reduce_sum_256(float v, float* red) {
    #pragma unroll
    for (int o = 16; o; o >>= 1) v += __shfl_xor_sync(0xffffffffu, v, o);
    int t = threadIdx.x;
    if ((t & 31) == 0) red[t >> 5] = v;
    __syncthreads();
    float z = (t < 8) ? red[t] : 0.f;
    if (t < 32) {
        #pragma unroll
        for (int o = 4; o; o >>= 1) z += __shfl_xor_sync(0xffffffffu, z, o);
        if (t == 0) red[0] = z;
    }
    __syncthreads();
    float r = red[0];
    __syncthreads();
    return r;
}

// ---------- kernel 1: LN + cyclic shift(-4,-4) + window partition ----------
// grid (65536, 2): y=0 -> x0 path, y=1 -> x1 path. 256 threads = one token.
__global__ void __launch_bounds__(256) ln_shift_part(
    const float* __restrict__ x0, const float* __restrict__ x1,
    const float* __restrict__ g0, const float* __restrict__ b0,
    const float* __restrict__ g1, const float* __restrict__ b1)
{
    __shared__ float red[8];
    int outTok = blockIdx.x;          // window-layout token index
    int which  = blockIdx.y;
    int win = outTok >> 6, n = outTok & 63;
    int b   = win >> 6,  nw = win & 63;
    int ys  = (nw >> 3) * WSZ + (n >> 3);
    int xs  = (nw & 7) * WSZ + (n & 7);
    int y = (ys + SHIFTW) & 63;       // roll(-SHIFT): shifted[i] = src[(i+SHIFT)%64]
    int x = (xs + SHIFTW) & 63;
    const float* src = (which ? x1 : x0) + ((size_t)(b * 4096 + y * 64 + x)) * DIMC;
    float*       dst = (which ? g_x1w : g_x0w) + (size_t)outTok * DIMC;
    const float* gg  = which ? g1 : g0;
    const float* bb  = which ? b1 : b0;

    int t = threadIdx.x;
    float v = src[t];
    float mean = block_reduce_sum_256(v, red) * (1.f / 256.f);
    float d = v - mean;
    float var = block_reduce_sum_256(d * d, red) * (1.f / 256.f);
    dst[t] = d * rsqrtf(var + 1e-5f) * gg[t] + bb[t];
}

// ---------------- kernel 6: plain LN of g_x -> g_xln -----------------------
__global__ void __launch_bounds__(256) ln_plain(
    const float* __restrict__ g2, const float* __restrict__ b2)
{
    __shared__ float red[8];
    size_t base = (size_t)blockIdx.x * DIMC;
    int t = threadIdx.x;
    float v = g_x[base + t];
    float mean = block_reduce_sum_256(v, red) * (1.f / 256.f);
    float d = v - mean;
    float var = block_reduce_sum_256(d * d, red) * (1.f / 256.f);
    g_xln[base + t] = d * rsqrtf(var + 1e-5f) * g2[t] + b2[t];
}

// ----------------------------- fused GEMMs --------------------------------
// C[M x Ncol] = A[M x K] @ W^T (+bias, + mode-specific epilogue)
// 128x128 block tile, 256 threads, 8x8 per thread.
// MODE 0: q projection  (A=g_x1w, scale, head-major store)
// MODE 1: kv projection (A=g_x0w, split k/v, head-major store)
// MODE 2: out proj      (A=g_ao,  window-reverse + unshift + residual x1 -> g_x)
// MODE 3: fc1 + gelu    (A=g_xln -> g_h)
// MODE 4: fc2 + resid   (A=g_h   -> d_out)
template<int MODE>
__global__ void __launch_bounds__(256) gemm_kernel(
    const float* __restrict__ W, const float* __restrict__ bias,
    int K, const float* __restrict__ extra, float* __restrict__ out)
{
    const float* A = (MODE == 0) ? g_x1w :
                     (MODE == 1) ? g_x0w :
                     (MODE == 2) ? g_ao  :
                     (MODE == 3) ? g_xln : g_h;

    __shared__ float As[16][128];
    __shared__ float Ws[16][128];

    int tid = threadIdx.x;
    int tx = tid & 15, ty = tid >> 4;
    int rowBase = blockIdx.y * 128;
    int colBase = blockIdx.x * 128;

    float acc[8][8];
    #pragma unroll
    for (int i = 0; i < 8; i++)
        #pragma unroll
        for (int j = 0; j < 8; j++) acc[i][j] = 0.f;

    int lrow = tid >> 2;            // 0..63
    int lk   = (tid & 3) * 4;       // 0,4,8,12

    for (int k0 = 0; k0 < K; k0 += 16) {
        float4 a0 = *(const float4*)&A[(size_t)(rowBase + lrow)      * K + k0 + lk];
        float4 a1 = *(const float4*)&A[(size_t)(rowBase + lrow + 64) * K + k0 + lk];
        float4 w0 = *(const float4*)&W[(size_t)(colBase + lrow)      * K + k0 + lk];
        float4 w1 = *(const float4*)&W[(size_t)(colBase + lrow + 64) * K + k0 + lk];
        __syncthreads();
        As[lk+0][lrow] = a0.x; As[lk+1][lrow] = a0.y; As[lk+2][lrow] = a0.z; As[lk+3][lrow] = a0.w;
        As[lk+0][lrow+64] = a1.x; As[lk+1][lrow+64] = a1.y; As[lk+2][lrow+64] = a1.z; As[lk+3][lrow+64] = a1.w;
        Ws[lk+0][lrow] = w0.x; Ws[lk+1][lrow] = w0.y; Ws[lk+2][lrow] = w0.z; Ws[lk+3][lrow] = w0.w;
        Ws[lk+0][lrow+64] = w1.x; Ws[lk+1][lrow+64] = w1.y; Ws[lk+2][lrow+64] = w1.z; Ws[lk+3][lrow+64] = w1.w;
        __syncthreads();
        #pragma unroll
        for (int kk = 0; kk < 16; kk++) {
            float4 av0 = *(const float4*)&As[kk][ty * 8];
            float4 av1 = *(const float4*)&As[kk][ty * 8 + 4];
            float4 wv0 = *(const float4*)&Ws[kk][tx * 8];
            float4 wv1 = *(const float4*)&Ws[kk][tx * 8 + 4];
            float a[8] = {av0.x, av0.y, av0.z, av0.w, av1.x, av1.y, av1.z, av1.w};
            float w[8] = {wv0.x, wv0.y, wv0.z, wv0.w, wv1.x, wv1.y, wv1.z, wv1.w};
            #pragma unroll
            for (int i = 0; i < 8; i++)
                #pragma unroll
                for (int j = 0; j < 8; j++)
                    acc[i][j] += a[i] * w[j];
        }
    }

    #pragma unroll
    for (int i = 0; i < 8; i++) {
        int m = rowBase + ty * 8 + i;
        #pragma unroll
        for (int j = 0; j < 8; j++) {
            int cg = colBase + tx * 8 + j;
            float val = acc[i][j] + bias[cg];
            if (MODE == 0) {                       // q, scaled, (win,head,n,d)
                val *= QSCALE;
                int win = m >> 6, n = m & 63, hd = cg >> 5, d = cg & 31;
                g_q[(((size_t)win * 8 + hd) * 64 + n) * 32 + d] = val;
            } else if (MODE == 1) {                // k / v
                int win = m >> 6, n = m & 63;
                int c2 = cg & 255, hd = c2 >> 5, d = c2 & 31;
                size_t idx = (((size_t)win * 8 + hd) * 64 + n) * 32 + d;
                if (cg < 256) g_k[idx] = val; else g_v[idx] = val;
            } else if (MODE == 2) {                // proj + win-reverse + unshift + residual
                int win = m >> 6, n = m & 63;
                int b = win >> 6, nw = win & 63;
                int y = ((nw >> 3) * WSZ + (n >> 3) + SHIFTW) & 63;
                int x = ((nw & 7) * WSZ + (n & 7) + SHIFTW) & 63;
                size_t t = ((size_t)(b * 4096 + y * 64 + x)) * DIMC + cg;
                g_x[t] = extra[t] + val;           // extra = original x1
            } else if (MODE == 3) {                // fc1 + exact gelu
                val = 0.5f * val * (1.f + erff(val * 0.70710678118654752f));
                g_h[(size_t)m * 1024 + cg] = val;
            } else {                               // fc2 + residual -> d_out
                size_t t = (size_t)m * DIMC + cg;
                out[t] = g_x[t] + val;
            }
        }
    }
}

// ------------- kernel 4: per-(window,head) attention, N=64 -----------------
__global__ void __launch_bounds__(256) attn_kernel(const float* __restrict__ rpb)
{
    __shared__ float qs[64][33], ks[64][33], vs[64][33];
    __shared__ float ss[64][65];

    int blk  = blockIdx.x;           // win*8 + head
    int win  = blk >> 3, head = blk & 7;
    int tid  = threadIdx.x;
    size_t base = (size_t)blk * 2048;

    for (int l = tid; l < 2048; l += 256) {
        int rr = l >> 5, d = l & 31;
        qs[rr][d] = g_q[base + l];
        ks[rr][d] = g_k[base + l];
        vs[rr][d] = g_v[base + l];
    }
    __syncthreads();

    int i  = tid >> 2;               // row 0..63 (4 threads per row, same warp)
    int j0 = (tid & 3) << 4;         // 16-col segment

    float qr[32];
    #pragma unroll
    for (int d = 0; d < 32; d++) qr[d] = qs[i][d];

    // shifted-window mask labels (analytic)
    int nw  = win & 63;
    int whb = (nw >> 3) * WSZ, wwb = (nw & 7) * WSZ;
    int ri = i >> 3, ci = i & 7;
    int yi = whb + ri, xi = wwb + ci;
    int labi = (yi < 56 ? 0 : (yi < 60 ? 1 : 2)) * 3 + (xi < 56 ? 0 : (xi < 60 ? 1 : 2));

    #pragma unroll
    for (int jj = 0; jj < 16; jj++) {
        int j = j0 + jj;
        float a = 0.f;
        #pragma unroll
        for (int d = 0; d < 32; d++) a += qr[d] * ks[j][d];
        int rj = j >> 3, cj = j & 7;
        int rel = (ri - rj + 7) * 15 + (ci - cj + 7);
        a += __ldg(&rpb[rel * 8 + head]);
        int yj = whb + rj, xj = wwb + cj;
        int labj = (yj < 56 ? 0 : (yj < 60 ? 1 : 2)) * 3 + (xj < 56 ? 0 : (xj < 60 ? 1 : 2));
        if (labj != labi) a -= 100.f;
        ss[i][j] = a;
    }

    // softmax over the row (4 cooperating lanes in the same warp)
    float mx = -1e30f;
    #pragma unroll
    for (int jj = 0; jj < 16; jj++) mx = fmaxf(mx, ss[i][j0 + jj]);
    mx = fmaxf(mx, __shfl_xor_sync(0xffffffffu, mx, 1));
    mx = fmaxf(mx, __shfl_xor_sync(0xffffffffu, mx, 2));
    float ev[16], sm = 0.f;
    #pragma unroll
    for (int jj = 0; jj < 16; jj++) { ev[jj] = __expf(ss[i][j0 + jj] - mx); sm += ev[jj]; }
    sm += __shfl_xor_sync(0xffffffffu, sm, 1);
    sm += __shfl_xor_sync(0xffffffffu, sm, 2);
    float inv = 1.f / sm;
    #pragma unroll
    for (int jj = 0; jj < 16; jj++) ss[i][j0 + jj] = ev[jj] * inv;
    __syncwarp();                    // row i written entirely by this warp's lanes

    // O = P @ V  (each thread: row i, 8 d-columns)
    int d0 = (tid & 3) << 3;
    float o[8];
    #pragma unroll
    for (int dd = 0; dd < 8; dd++) o[dd] = 0.f;
    for (int j = 0; j < 64; j++) {
        float p = ss[i][j];
        #pragma unroll
        for (int dd = 0; dd < 8; dd++) o[dd] += p * vs[j][d0 + dd];
    }
    size_t ob = ((size_t)win * 64 + i) * DIMC + head * 32 + d0;
    #pragma unroll
    for (int dd = 0; dd < 8; dd++) g_ao[ob + dd] = o[dd];
}

// ------------------------------- launcher ----------------------------------
extern "C" void kernel_launch(void* const* d_in, const int* in_sizes, int n_in,
                              void* d_out, int out_size)
{
    const float* x0   = (const float*)d_in[0];
    const float* x1   = (const float*)d_in[1];
    const float* g1_0 = (const float*)d_in[2];
    const float* b1_0 = (const float*)d_in[3];
    const float* g1_1 = (const float*)d_in[4];
    const float* b1_1 = (const float*)d_in[5];
    const float* Wq   = (const float*)d_in[6];
    const float* bq   = (const float*)d_in[7];
    const float* Wkv  = (const float*)d_in[8];
    const float* bkv  = (const float*)d_in[9];
    const float* rpb  = (const float*)d_in[10];
    const float* Wp   = (const float*)d_in[11];
    const float* bp   = (const float*)d_in[12];
    const float* g2   = (const float*)d_in[13];
    const float* b2   = (const float*)d_in[14];
    const float* Wfc1 = (const float*)d_in[15];
    const float* bfc1 = (const float*)d_in[16];
    const float* Wfc2 = (const float*)d_in[17];
    const float* bfc2 = (const float*)d_in[18];
    float* out = (float*)d_out;

    ln_shift_part<<<dim3(MTOK, 2), 256>>>(x0, x1, g1_0, b1_0, g1_1, b1_1);
    gemm_kernel<0><<<dim3(2, 512), 256>>>(Wq,   bq,   256,  nullptr, nullptr);
    gemm_kernel<1><<<dim3(4, 512), 256>>>(Wkv,  bkv,  256,  nullptr, nullptr);
    attn_kernel<<<8192, 256>>>(rpb);
    gemm_kernel<2><<<dim3(2, 512), 256>>>(Wp,   bp,   256,  x1,      nullptr);
    ln_plain<<<MTOK, 256>>>(g2, b2);
    gemm_kernel<3><<<dim3(8, 512), 256>>>(Wfc1, bfc1, 256,  nullptr, nullptr);
    gemm_kernel<4><<<dim3(2, 512), 256>>>(Wfc2, bfc2, 1024, nullptr, out);
}

// round 2
// speedup vs baseline: 2.4309x; 2.4309x over previous
#include <cuda_runtime.h>
#include <cstdint>
#include <math.h>

#define DIMC   256
#define HEADS  8
#define DHEAD  32
#define WSZ    8
#define SHIFTW 4
#define IMGH   64
#define IMGW   64
#define BATCH  16
#define MTOK   (BATCH*IMGH*IMGW)     // 65536 tokens
#define QSCALE 0.17677669529663687f  // 32^-0.5

// -------- scratch (device globals; allocation-free at launch time) --------
__device__ float g_x0w[MTOK*DIMC];   // LN+shift+partition of x0 (kv source)
__device__ float g_x1w[MTOK*DIMC];   // LN+shift+partition of x1 (q source)
__device__ float g_q  [MTOK*DIMC];   // (win, head, n, d)
__device__ float g_k  [MTOK*DIMC];
__device__ float g_v  [MTOK*DIMC];
__device__ float g_ao [MTOK*DIMC];   // attention out, (win, n, dim)
__device__ float g_x  [MTOK*DIMC];   // residual stream after attention
__device__ float g_xln[MTOK*DIMC];   // LN2(x)
__device__ float g_h  [MTOK*4*DIMC]; // FC1 activations

// -------------------------- helpers ---------------------------------------
__device__ __forceinline__ float block_reduce_sum_256(float v, float* red) {
    #pragma unroll
    for (int o = 16; o; o >>= 1) v += __shfl_xor_sync(0xffffffffu, v, o);
    int t = threadIdx.x;
    if ((t & 31) == 0) red[t >> 5] = v;
    __syncthreads();
    float z = (t < 8) ? red[t] : 0.f;
    if (t < 32) {
        #pragma unroll
        for (int o = 4; o; o >>= 1) z += __shfl_xor_sync(0xffffffffu, z, o);
        if (t == 0) red[0] = z;
    }
    __syncthreads();
    float r = red[0];
    __syncthreads();
    return r;
}

__device__ __forceinline__ uint32_t f2tf(float x) {
    uint32_t r;
    asm("cvt.rna.tf32.f32 %0, %1;" : "=r"(r) : "f"(x));
    return r;
}

__device__ __forceinline__ void cp_async16(void* smem_dst, const void* gmem_src) {
    uint32_t s = (uint32_t)__cvta_generic_to_shared(smem_dst);
    asm volatile("cp.async.cg.shared.global [%0], [%1], 16;\n" :: "r"(s), "l"(gmem_src));
}
__device__ __forceinline__ void cp_commit() { asm volatile("cp.async.commit_group;\n"); }
__device__ __forceinline__ void cp_wait1()  { asm volatile("cp.async.wait_group 1;\n"); }
__device__ __forceinline__ void cp_wait0()  { asm volatile("cp.async.wait_group 0;\n"); }

__device__ __forceinline__ void mma_tf32(float c[4], const uint32_t a[4], const uint32_t b[2]) {
    asm volatile(
        "mma.sync.aligned.m16n8k8.row.col.f32.tf32.tf32.f32 "
        "{%0,%1,%2,%3}, {%4,%5,%6,%7}, {%8,%9}, {%0,%1,%2,%3};"
        : "+f"(c[0]), "+f"(c[1]), "+f"(c[2]), "+f"(c[3])
        : "r"(a[0]), "r"(a[1]), "r"(a[2]), "r"(a[3]), "r"(b[0]), "r"(b[1]));
}

// ---------- kernel 1: LN + cyclic shift(-4,-4) + window partition ----------
__global__ void __launch_bounds__(256) ln_shift_part(
    const float* __restrict__ x0, const float* __restrict__ x1,
    const float* __restrict__ g0, const float* __restrict__ b0,
    const float* __restrict__ g1, const float* __restrict__ b1)
{
    __shared__ float red[8];
    int outTok = blockIdx.x;
    int which  = blockIdx.y;
    int win = outTok >> 6, n = outTok & 63;
    int b   = win >> 6,  nw = win & 63;
    int ys  = (nw >> 3) * WSZ + (n >> 3);
    int xs  = (nw & 7) * WSZ + (n & 7);
    int y = (ys + SHIFTW) & 63;
    int x = (xs + SHIFTW) & 63;
    const float* src = (which ? x1 : x0) + ((size_t)(b * 4096 + y * 64 + x)) * DIMC;
    float*       dst = (which ? g_x1w : g_x0w) + (size_t)outTok * DIMC;
    const float* gg  = which ? g1 : g0;
    const float* bb  = which ? b1 : b0;

    int t = threadIdx.x;
    float v = src[t];
    float mean = block_reduce_sum_256(v, red) * (1.f / 256.f);
    float d = v - mean;
    float var = block_reduce_sum_256(d * d, red) * (1.f / 256.f);
    dst[t] = d * rsqrtf(var + 1e-5f) * gg[t] + bb[t];
}

// ---------------- plain LN of g_x -> g_xln ---------------------------------
__global__ void __launch_bounds__(256) ln_plain(
    const float* __restrict__ g2, const float* __restrict__ b2)
{
    __shared__ float red[8];
    size_t base = (size_t)blockIdx.x * DIMC;
    int t = threadIdx.x;
    float v = g_x[base + t];
    float mean = block_reduce_sum_256(v, red) * (1.f / 256.f);
    float d = v - mean;
    float var = block_reduce_sum_256(d * d, red) * (1.f / 256.f);
    g_xln[base + t] = d * rsqrtf(var + 1e-5f) * g2[t] + b2[t];
}

// ----------------------- TF32 tensor-core GEMMs ----------------------------
// C[M x N] = A[M x K] @ W^T (+bias + mode-specific epilogue)
// 128x128 block tile, BK=16, 256 threads (8 warps, 2x4), warp tile 64x32.
// MODE 0: q proj (scale, head-major)  MODE 1: kv proj (split k/v, head-major)
// MODE 2: out proj (+win-reverse +unshift +residual)  MODE 3: fc1+gelu
// MODE 4: fc2 + residual -> out
#define BK 16
#define ASTRIDE 20   // stride so frag-load bank = (20*gr + lc) mod 32 : permutation

template<int MODE>
__device__ __forceinline__ void emit_elem(int m, int cg, float val,
    const float* __restrict__ bias, const float* __restrict__ extra,
    float* __restrict__ out)
{
    val += __ldg(&bias[cg]);
    if (MODE == 0) {
        val *= QSCALE;
        int win = m >> 6, n = m & 63, hd = cg >> 5, d = cg & 31;
        g_q[(((size_t)win * 8 + hd) * 64 + n) * 32 + d] = val;
    } else if (MODE == 1) {
        int win = m >> 6, n = m & 63;
        int c2 = cg & 255, hd = c2 >> 5, d = c2 & 31;
        size_t idx = (((size_t)win * 8 + hd) * 64 + n) * 32 + d;
        if (cg < 256) g_k[idx] = val; else g_v[idx] = val;
    } else if (MODE == 2) {
        int win = m >> 6, n = m & 63;
        int b = win >> 6, nw = win & 63;
        int y = ((nw >> 3) * WSZ + (n >> 3) + SHIFTW) & 63;
        int x = ((nw & 7) * WSZ + (n & 7) + SHIFTW) & 63;
        size_t t = ((size_t)(b * 4096 + y * 64 + x)) * DIMC + cg;
        g_x[t] = extra[t] + val;
    } else if (MODE == 3) {
        val = 0.5f * val * (1.f + erff(val * 0.70710678118654752f));
        g_h[(size_t)m * 1024 + cg] = val;
    } else {
        size_t t = (size_t)m * DIMC + cg;
        out[t] = g_x[t] + val;
    }
}

template<int MODE>
__global__ void __launch_bounds__(256) mma_gemm(
    const float* __restrict__ W, const float* __restrict__ bias,
    int K, const float* __restrict__ extra, float* __restrict__ out)
{
    const float* A = (MODE == 0) ? g_x1w :
                     (MODE == 1) ? g_x0w :
                     (MODE == 2) ? g_ao  :
                     (MODE == 3) ? g_xln : g_h;

    __shared__ float As[2][128][ASTRIDE];
    __shared__ float Ws[2][128][ASTRIDE];

    int tid  = threadIdx.x;
    int lane = tid & 31, warp = tid >> 5;
    int gr = lane >> 2, lc = lane & 3;
    int mWarp = (warp >> 2) * 64;
    int nWarp = (warp & 3) * 32;
    int rowBase = blockIdx.y * 128;
    int colBase = blockIdx.x * 128;

    // loader mapping: 2 float4 per array per thread per stage
    int lrow0 = tid >> 2;         // 0..63
    int lk4   = tid & 3;          // 0..3 (float4 index within 16-float row)
    const float* Abase = A + (size_t)rowBase * K + lk4 * 4;
    const float* Wbase = W + (size_t)colBase * K + lk4 * 4;

    float acc[4][4][4];
    #pragma unroll
    for (int mi = 0; mi < 4; mi++)
        #pragma unroll
        for (int ni = 0; ni < 4; ni++)
            #pragma unroll
            for (int e = 0; e < 4; e++) acc[mi][ni][e] = 0.f;

    int nK = K / BK;

    // prefetch stage 0
    {
        const float* a0 = Abase + (size_t)lrow0 * K;
        const float* a1 = Abase + (size_t)(lrow0 + 64) * K;
        const float* w0 = Wbase + (size_t)lrow0 * K;
        const float* w1 = Wbase + (size_t)(lrow0 + 64) * K;
        cp_async16(&As[0][lrow0][lk4 * 4], a0);
        cp_async16(&As[0][lrow0 + 64][lk4 * 4], a1);
        cp_async16(&Ws[0][lrow0][lk4 * 4], w0);
        cp_async16(&Ws[0][lrow0 + 64][lk4 * 4], w1);
        cp_commit();
    }

    for (int s = 0; s < nK; ++s) {
        if (s + 1 < nK) {
            int nb = (s + 1) & 1;
            size_t koff = (size_t)(s + 1) * BK;
            cp_async16(&As[nb][lrow0][lk4 * 4],      Abase + (size_t)lrow0 * K + koff);
            cp_async16(&As[nb][lrow0 + 64][lk4 * 4], Abase + (size_t)(lrow0 + 64) * K + koff);
            cp_async16(&Ws[nb][lrow0][lk4 * 4],      Wbase + (size_t)lrow0 * K + koff);
            cp_async16(&Ws[nb][lrow0 + 64][lk4 * 4], Wbase + (size_t)(lrow0 + 64) * K + koff);
            cp_commit();
            cp_wait1();
        } else {
            cp_wait0();
        }
        __syncthreads();

        int buf = s & 1;
        #pragma unroll
        for (int ks = 0; ks < 2; ++ks) {
            int kb = ks * 8;
            uint32_t a[4][4], b[4][2];
            #pragma unroll
            for (int mi = 0; mi < 4; mi++) {
                int m = mWarp + mi * 16 + gr;
                a[mi][0] = f2tf(As[buf][m][kb + lc]);
                a[mi][1] = f2tf(As[buf][m + 8][kb + lc]);
                a[mi][2] = f2tf(As[buf][m][kb + lc + 4]);
                a[mi][3] = f2tf(As[buf][m + 8][kb + lc + 4]);
            }
            #pragma unroll
            for (int ni = 0; ni < 4; ni++) {
                int n = nWarp + ni * 8 + gr;
                b[ni][0] = f2tf(Ws[buf][n][kb + lc]);
                b[ni][1] = f2tf(Ws[buf][n][kb + lc + 4]);
            }
            #pragma unroll
            for (int mi = 0; mi < 4; mi++)
                #pragma unroll
                for (int ni = 0; ni < 4; ni++)
                    mma_tf32(acc[mi][ni], a[mi], b[ni]);
        }
        __syncthreads();
    }

    // epilogue
    #pragma unroll
    for (int mi = 0; mi < 4; mi++) {
        int r0 = rowBase + mWarp + mi * 16 + gr;
        #pragma unroll
        for (int ni = 0; ni < 4; ni++) {
            int c0 = colBase + nWarp + ni * 8 + lc * 2;
            emit_elem<MODE>(r0,     c0,     acc[mi][ni][0], bias, extra, out);
            emit_elem<MODE>(r0,     c0 + 1, acc[mi][ni][1], bias, extra, out);
            emit_elem<MODE>(r0 + 8, c0,     acc[mi][ni][2], bias, extra, out);
            emit_elem<MODE>(r0 + 8, c0 + 1, acc[mi][ni][3], bias, extra, out);
        }
    }
}

// ------------- attention: per-(window,head), N=64, vectorized --------------
__global__ void __launch_bounds__(256) attn_kernel(const float* __restrict__ rpb)
{
    __shared__ float4 qs4[64][8], ks4[64][8], vs4[64][8];
    __shared__ float  ss[64][65];

    int blk  = blockIdx.x;           // win*8 + head
    int win  = blk >> 3, head = blk & 7;
    int tid  = threadIdx.x;
    size_t base = (size_t)blk * 2048;

    const float4* q4 = reinterpret_cast<const float4*>(g_q + base);
    const float4* k4 = reinterpret_cast<const float4*>(g_k + base);
    const float4* v4 = reinterpret_cast<const float4*>(g_v + base);
    #pragma unroll
    for (int f = tid; f < 512; f += 256) {
        int row = f >> 3, d4 = f & 7;
        qs4[row][d4 ^ (row & 7)]         = q4[f];
        ks4[row][d4 ^ ((row >> 4) & 3)]  = k4[f];
        vs4[row][d4 ^ (row & 7)]         = v4[f];
    }
    __syncthreads();

    int i  = tid >> 2;               // row 0..63 (4 lanes per row, same warp)
    int j0 = (tid & 3) << 4;         // 16-col segment

    float4 qr[8];
    #pragma unroll
    for (int d4 = 0; d4 < 8; d4++) qr[d4] = qs4[i][d4 ^ (i & 7)];

    // shifted-window mask labels (analytic)
    int nw  = win & 63;
    int whb = (nw >> 3) * WSZ, wwb = (nw & 7) * WSZ;
    int ri = i >> 3, ci = i & 7;
    int yi = whb + ri, xi = wwb + ci;
    int labi = (yi < 56 ? 0 : (yi < 60 ? 1 : 2)) * 3 + (xi < 56 ? 0 : (xi < 60 ? 1 : 2));

    #pragma unroll
    for (int jj = 0; jj < 16; jj++) {
        int j = j0 + jj;
        int jsw = (j >> 4) & 3;
        float a = 0.f;
        #pragma unroll
        for (int d4 = 0; d4 < 8; d4++) {
            float4 kv = ks4[j][d4 ^ jsw];
            a += qr[d4].x * kv.x + qr[d4].y * kv.y + qr[d4].z * kv.z + qr[d4].w * kv.w;
        }
        int rj = j >> 3, cj = j & 7;
        int rel = (ri - rj + 7) * 15 + (ci - cj + 7);
        a += __ldg(&rpb[rel * 8 + head]);
        int yj = whb + rj, xj = wwb + cj;
        int labj = (yj < 56 ? 0 : (yj < 60 ? 1 : 2)) * 3 + (xj < 56 ? 0 : (xj < 60 ? 1 : 2));
        if (labj != labi) a -= 100.f;
        ss[i][j] = a;
    }

    // softmax across the 4 cooperating lanes
    float mx = -1e30f;
    #pragma unroll
    for (int jj = 0; jj < 16; jj++) mx = fmaxf(mx, ss[i][j0 + jj]);
    mx = fmaxf(mx, __shfl_xor_sync(0xffffffffu, mx, 1));
    mx = fmaxf(mx, __shfl_xor_sync(0xffffffffu, mx, 2));
    float ev[16], sm = 0.f;
    #pragma unroll
    for (int jj = 0; jj < 16; jj++) { ev[jj] = __expf(ss[i][j0 + jj] - mx); sm += ev[jj]; }
    sm += __shfl_xor_sync(0xffffffffu, sm, 1);
    sm += __shfl_xor_sync(0xffffffffu, sm, 2);
    float inv = 1.f / sm;
    #pragma unroll
    for (int jj = 0; jj < 16; jj++) ss[i][j0 + jj] = ev[jj] * inv;
    __syncwarp();

    // O = P @ V  (row i, 8 d-columns = 2 float4 slots)
    int q0 = (tid & 3) * 2;
    float4 o0 = {0.f, 0.f, 0.f, 0.f}, o1 = {0.f, 0.f, 0.f, 0.f};
    #pragma unroll 4
    for (int j = 0; j < 64; j++) {
        float p = ss[i][j];
        int jsw = j & 7;
        float4 v0 = vs4[j][q0 ^ jsw];
        float4 v1 = vs4[j][(q0 + 1) ^ jsw];
        o0.x += p * v0.x; o0.y += p * v0.y; o0.z += p * v0.z; o0.w += p * v0.w;
        o1.x += p * v1.x; o1.y += p * v1.y; o1.z += p * v1.z; o1.w += p * v1.w;
    }
    size_t ob = ((size_t)win * 64 + i) * DIMC + head * 32 + q0 * 4;
    float4* outp = reinterpret_cast<float4*>(g_ao + ob);
    outp[0] = o0;
    outp[1] = o1;
}

// ------------------------------- launcher ----------------------------------
extern "C" void kernel_launch(void* const* d_in, const int* in_sizes, int n_in,
                              void* d_out, int out_size)
{
    const float* x0   = (const float*)d_in[0];
    const float* x1   = (const float*)d_in[1];
    const float* g1_0 = (const float*)d_in[2];
    const float* b1_0 = (const float*)d_in[3];
    const float* g1_1 = (const float*)d_in[4];
    const float* b1_1 = (const float*)d_in[5];
    const float* Wq   = (const float*)d_in[6];
    const float* bq   = (const float*)d_in[7];
    const float* Wkv  = (const float*)d_in[8];
    const float* bkv  = (const float*)d_in[9];
    const float* rpb  = (const float*)d_in[10];
    const float* Wp   = (const float*)d_in[11];
    const float* bp   = (const float*)d_in[12];
    const float* g2   = (const float*)d_in[13];
    const float* b2   = (const float*)d_in[14];
    const float* Wfc1 = (const float*)d_in[15];
    const float* bfc1 = (const float*)d_in[16];
    const float* Wfc2 = (const float*)d_in[17];
    const float* bfc2 = (const float*)d_in[18];
    float* out = (float*)d_out;

    ln_shift_part<<<dim3(MTOK, 2), 256>>>(x0, x1, g1_0, b1_0, g1_1, b1_1);
    mma_gemm<0><<<dim3(2, 512), 256>>>(Wq,   bq,   256,  nullptr, nullptr);
    mma_gemm<1><<<dim3(4, 512), 256>>>(Wkv,  bkv,  256,  nullptr, nullptr);
    attn_kernel<<<8192, 256>>>(rpb);
    mma_gemm<2><<<dim3(2, 512), 256>>>(Wp,   bp,   256,  x1,      nullptr);
    ln_plain<<<MTOK, 256>>>(g2, b2);
    mma_gemm<3><<<dim3(8, 512), 256>>>(Wfc1, bfc1, 256,  nullptr, nullptr);
    mma_gemm<4><<<dim3(2, 512), 256>>>(Wfc2, bfc2, 1024, nullptr, out);
}

// round 3
// speedup vs baseline: 3.7939x; 1.5607x over previous
#include <cuda_runtime.h>
#include <cuda_bf16.h>
#include <cstdint>
#include <math.h>

#define DIMC   256
#define HEADS  8
#define WSZ    8
#define SHIFTW 4
#define BATCH  16
#define MTOK   (BATCH*64*64)         // 65536 tokens
#define QSCALE 0.17677669529663687f  // 32^-0.5

typedef __nv_bfloat16 bf16;

// -------- scratch (device globals) --------
__device__ bf16  g_x0w[MTOK*DIMC];   // LN+shift+partition of x0 (kv source)
__device__ bf16  g_x1w[MTOK*DIMC];   // LN+shift+partition of x1 (q source)
__device__ bf16  g_q  [MTOK*DIMC];   // (win, head, n, d)
__device__ bf16  g_k  [MTOK*DIMC];
__device__ bf16  g_v  [MTOK*DIMC];
__device__ bf16  g_ao [MTOK*DIMC];   // attention out (win, n, dim)
__device__ float g_x  [MTOK*DIMC];   // residual stream (fp32!)
__device__ bf16  g_xln[MTOK*DIMC];
__device__ bf16  g_h  [MTOK*4*DIMC];
// bf16 weights
__device__ bf16 g_bWq [DIMC*DIMC];
__device__ bf16 g_bWkv[2*DIMC*DIMC];
__device__ bf16 g_bWp [DIMC*DIMC];
__device__ bf16 g_bW1 [4*DIMC*DIMC];
__device__ bf16 g_bW2 [4*DIMC*DIMC];

// -------------------------- helpers ---------------------------------------
__device__ __forceinline__ float block_reduce_sum_256(float v, float* red) {
    #pragma unroll
    for (int o = 16; o; o >>= 1) v += __shfl_xor_sync(0xffffffffu, v, o);
    int t = threadIdx.x;
    if ((t & 31) == 0) red[t >> 5] = v;
    __syncthreads();
    float z = (t < 8) ? red[t] : 0.f;
    if (t < 32) {
        #pragma unroll
        for (int o = 4; o; o >>= 1) z += __shfl_xor_sync(0xffffffffu, z, o);
        if (t == 0) red[0] = z;
    }
    __syncthreads();
    float r = red[0];
    __syncthreads();
    return r;
}

__device__ __forceinline__ void cp_async16(void* smem_dst, const void* gmem_src) {
    uint32_t s = (uint32_t)__cvta_generic_to_shared(smem_dst);
    asm volatile("cp.async.cg.shared.global [%0], [%1], 16;\n" :: "r"(s), "l"(gmem_src));
}
__device__ __forceinline__ void cp_commit() { asm volatile("cp.async.commit_group;\n"); }
__device__ __forceinline__ void cp_wait1()  { asm volatile("cp.async.wait_group 1;\n"); }
__device__ __forceinline__ void cp_wait0()  { asm volatile("cp.async.wait_group 0;\n"); }

__device__ __forceinline__ void mma_bf16(float c[4], const uint32_t a[4], const uint32_t b[2]) {
    asm volatile(
        "mma.sync.aligned.m16n8k16.row.col.f32.bf16.bf16.f32 "
        "{%0,%1,%2,%3}, {%4,%5,%6,%7}, {%8,%9}, {%0,%1,%2,%3};"
        : "+f"(c[0]), "+f"(c[1]), "+f"(c[2]), "+f"(c[3])
        : "r"(a[0]), "r"(a[1]), "r"(a[2]), "r"(a[3]), "r"(b[0]), "r"(b[1]));
}

__device__ __forceinline__ void ldsm4(uint32_t& r0, uint32_t& r1, uint32_t& r2, uint32_t& r3, uint32_t addr) {
    asm volatile("ldmatrix.sync.aligned.m8n8.x4.shared.b16 {%0,%1,%2,%3}, [%4];"
        : "=r"(r0), "=r"(r1), "=r"(r2), "=r"(r3) : "r"(addr));
}
__device__ __forceinline__ void ldsm4t(uint32_t& r0, uint32_t& r1, uint32_t& r2, uint32_t& r3, uint32_t addr) {
    asm volatile("ldmatrix.sync.aligned.m8n8.x4.trans.shared.b16 {%0,%1,%2,%3}, [%4];"
        : "=r"(r0), "=r"(r1), "=r"(r2), "=r"(r3) : "r"(addr));
}

__device__ __forceinline__ uint32_t pack_bf16(float lo, float hi) {
    uint32_t r;
    asm("cvt.rn.bf16x2.f32 %0, %1, %2;" : "=r"(r) : "f"(hi), "f"(lo));
    return r;
}

// ---------------------- weight conversion fp32 -> bf16 ---------------------
__global__ void __launch_bounds__(256) convert_weights(
    const float* __restrict__ Wq, const float* __restrict__ Wkv,
    const float* __restrict__ Wp, const float* __restrict__ W1,
    const float* __restrict__ W2)
{
    int which = blockIdx.y;
    const float* src; bf16* dst; int n;
    if      (which == 0) { src = Wq;  dst = g_bWq;  n = DIMC*DIMC; }
    else if (which == 1) { src = Wkv; dst = g_bWkv; n = 2*DIMC*DIMC; }
    else if (which == 2) { src = Wp;  dst = g_bWp;  n = DIMC*DIMC; }
    else if (which == 3) { src = W1;  dst = g_bW1;  n = 4*DIMC*DIMC; }
    else                 { src = W2;  dst = g_bW2;  n = 4*DIMC*DIMC; }
    for (int i = blockIdx.x * 256 + threadIdx.x; i < n; i += gridDim.x * 256)
        dst[i] = __float2bfloat16(src[i]);
}

// ---------- LN + cyclic shift(-4,-4) + window partition -> bf16 ------------
__global__ void __launch_bounds__(256) ln_shift_part(
    const float* __restrict__ x0, const float* __restrict__ x1,
    const float* __restrict__ g0, const float* __restrict__ b0,
    const float* __restrict__ g1, const float* __restrict__ b1)
{
    __shared__ float red[8];
    int outTok = blockIdx.x;
    int which  = blockIdx.y;
    int win = outTok >> 6, n = outTok & 63;
    int b   = win >> 6,  nw = win & 63;
    int y = ((nw >> 3) * WSZ + (n >> 3) + SHIFTW) & 63;
    int x = ((nw & 7) * WSZ + (n & 7) + SHIFTW) & 63;
    const float* src = (which ? x1 : x0) + ((size_t)(b * 4096 + y * 64 + x)) * DIMC;
    bf16*        dst = (which ? g_x1w : g_x0w) + (size_t)outTok * DIMC;
    const float* gg  = which ? g1 : g0;
    const float* bb  = which ? b1 : b0;

    int t = threadIdx.x;
    float v = src[t];
    float mean = block_reduce_sum_256(v, red) * (1.f / 256.f);
    float d = v - mean;
    float var = block_reduce_sum_256(d * d, red) * (1.f / 256.f);
    dst[t] = __float2bfloat16(d * rsqrtf(var + 1e-5f) * gg[t] + bb[t]);
}

// ---------------- plain LN of g_x (fp32) -> g_xln (bf16) -------------------
__global__ void __launch_bounds__(256) ln_plain(
    const float* __restrict__ g2, const float* __restrict__ b2)
{
    __shared__ float red[8];
    size_t base = (size_t)blockIdx.x * DIMC;
    int t = threadIdx.x;
    float v = g_x[base + t];
    float mean = block_reduce_sum_256(v, red) * (1.f / 256.f);
    float d = v - mean;
    float var = block_reduce_sum_256(d * d, red) * (1.f / 256.f);
    g_xln[base + t] = __float2bfloat16(d * rsqrtf(var + 1e-5f) * g2[t] + b2[t]);
}

// ----------------------- bf16 tensor-core GEMMs ----------------------------
// C[M x N] = A[M x K] @ W^T (+bias + epilogue). 128x128 tile, BK=32,
// 256 threads / 8 warps (2x4), warp tile 64x32, ldmatrix + m16n8k16.
#define BK 32
#define SST 40   // smem row stride in bf16 elems (80B, 16B-aligned, conflict-free)

template<int MODE>
__device__ __forceinline__ void emit_elem(int m, int cg, float val,
    const float* __restrict__ bias, const float* __restrict__ extra,
    float* __restrict__ out)
{
    val += __ldg(&bias[cg]);
    if (MODE == 0) {
        val *= QSCALE;
        int win = m >> 6, n = m & 63, hd = cg >> 5, d = cg & 31;
        g_q[(((size_t)win * 8 + hd) * 64 + n) * 32 + d] = __float2bfloat16(val);
    } else if (MODE == 1) {
        int win = m >> 6, n = m & 63;
        int c2 = cg & 255, hd = c2 >> 5, d = c2 & 31;
        size_t idx = (((size_t)win * 8 + hd) * 64 + n) * 32 + d;
        if (cg < 256) g_k[idx] = __float2bfloat16(val);
        else          g_v[idx] = __float2bfloat16(val);
    } else if (MODE == 2) {
        int win = m >> 6, n = m & 63;
        int b = win >> 6, nw = win & 63;
        int y = ((nw >> 3) * WSZ + (n >> 3) + SHIFTW) & 63;
        int x = ((nw & 7) * WSZ + (n & 7) + SHIFTW) & 63;
        size_t t = ((size_t)(b * 4096 + y * 64 + x)) * DIMC + cg;
        g_x[t] = extra[t] + val;
    } else if (MODE == 3) {
        val = 0.5f * val * (1.f + erff(val * 0.70710678118654752f));
        g_h[(size_t)m * 1024 + cg] = __float2bfloat16(val);
    } else {
        size_t t = (size_t)m * DIMC + cg;
        out[t] = g_x[t] + val;
    }
}

template<int MODE>
__global__ void __launch_bounds__(256) mma_gemm(
    const bf16* __restrict__ W, const float* __restrict__ bias,
    int K, const float* __restrict__ extra, float* __restrict__ out)
{
    const bf16* A = (MODE == 0) ? g_x1w :
                    (MODE == 1) ? g_x0w :
                    (MODE == 2) ? g_ao  :
                    (MODE == 3) ? g_xln : g_h;

    __shared__ bf16 As[2][128][SST];
    __shared__ bf16 Ws[2][128][SST];

    int tid  = threadIdx.x;
    int lane = tid & 31, warp = tid >> 5;
    int gr = lane >> 2, lc = lane & 3;
    int mWarp = (warp >> 2) * 64;
    int nWarp = (warp & 3) * 32;
    int rowBase = blockIdx.y * 128;
    int colBase = blockIdx.x * 128;

    // loader mapping: chunks c=tid (rows 0..63) and c=tid+256 (rows 64..127)
    int lr = tid >> 2;            // 0..63
    int lk8 = (tid & 3) * 8;      // 0,8,16,24
    const bf16* Abase = A + (size_t)(rowBase) * K + lk8;
    const bf16* Wbase = W + (size_t)(colBase) * K + lk8;

    // per-lane ldmatrix offsets
    int mm = lane >> 3, r8 = lane & 7;
    int aRow = (mm & 1) * 8 + r8, aK = (mm >> 1) * 8;   // A matrices
    int bRow = (mm >> 1) * 8 + r8, bKo = (mm & 1) * 8;  // B matrices
    uint32_t A0 = (uint32_t)__cvta_generic_to_shared(&As[0][0][0]);
    uint32_t W0 = (uint32_t)__cvta_generic_to_shared(&Ws[0][0][0]);
    uint32_t aAddr = A0 + ((mWarp + aRow) * SST + aK) * 2;
    uint32_t bAddr = W0 + ((nWarp + bRow) * SST + bKo) * 2;
    const uint32_t BUFSZ = 128 * SST * 2;

    float acc[4][4][4];
    #pragma unroll
    for (int mi = 0; mi < 4; mi++)
        #pragma unroll
        for (int ni = 0; ni < 4; ni++)
            #pragma unroll
            for (int e = 0; e < 4; e++) acc[mi][ni][e] = 0.f;

    int nK = K / BK;

    // prefetch stage 0
    cp_async16(&As[0][lr][lk8],      Abase + (size_t)lr * K);
    cp_async16(&As[0][lr + 64][lk8], Abase + (size_t)(lr + 64) * K);
    cp_async16(&Ws[0][lr][lk8],      Wbase + (size_t)lr * K);
    cp_async16(&Ws[0][lr + 64][lk8], Wbase + (size_t)(lr + 64) * K);
    cp_commit();

    for (int s = 0; s < nK; ++s) {
        if (s + 1 < nK) {
            int nb = (s + 1) & 1;
            size_t koff = (size_t)(s + 1) * BK;
            cp_async16(&As[nb][lr][lk8],      Abase + (size_t)lr * K + koff);
            cp_async16(&As[nb][lr + 64][lk8], Abase + (size_t)(lr + 64) * K + koff);
            cp_async16(&Ws[nb][lr][lk8],      Wbase + (size_t)lr * K + koff);
            cp_async16(&Ws[nb][lr + 64][lk8], Wbase + (size_t)(lr + 64) * K + koff);
            cp_commit();
            cp_wait1();
        } else {
            cp_wait0();
        }
        __syncthreads();

        uint32_t bufOff = (s & 1) ? BUFSZ : 0;
        #pragma unroll
        for (int ks = 0; ks < 2; ++ks) {
            int kb = ks * 16;
            uint32_t aF[4][4], bF[4][2];
            #pragma unroll
            for (int mi = 0; mi < 4; mi++)
                ldsm4(aF[mi][0], aF[mi][1], aF[mi][2], aF[mi][3],
                      aAddr + bufOff + (mi * 16 * SST + kb) * 2);
            ldsm4(bF[0][0], bF[0][1], bF[1][0], bF[1][1], bAddr + bufOff + kb * 2);
            ldsm4(bF[2][0], bF[2][1], bF[3][0], bF[3][1], bAddr + bufOff + (16 * SST + kb) * 2);
            #pragma unroll
            for (int mi = 0; mi < 4; mi++)
                #pragma unroll
                for (int ni = 0; ni < 4; ni++)
                    mma_bf16(acc[mi][ni], aF[mi], bF[ni]);
        }
        __syncthreads();
    }

    #pragma unroll
    for (int mi = 0; mi < 4; mi++) {
        int r0 = rowBase + mWarp + mi * 16 + gr;
        #pragma unroll
        for (int ni = 0; ni < 4; ni++) {
            int c0 = colBase + nWarp + ni * 8 + lc * 2;
            emit_elem<MODE>(r0,     c0,     acc[mi][ni][0], bias, extra, out);
            emit_elem<MODE>(r0,     c0 + 1, acc[mi][ni][1], bias, extra, out);
            emit_elem<MODE>(r0 + 8, c0,     acc[mi][ni][2], bias, extra, out);
            emit_elem<MODE>(r0 + 8, c0 + 1, acc[mi][ni][3], bias, extra, out);
        }
    }
}

// ------------- tensor-core attention: warp = (head, row-half) --------------
// grid = 1024 windows * 2 halves; block 256 thr / 8 warps (one head each).
#define VST 40
__global__ void __launch_bounds__(256) attn_kernel(const float* __restrict__ rpb)
{
    __shared__ bf16 vs[8][64][VST];   // 40960 B

    int blk  = blockIdx.x;
    int win  = blk >> 1, half = blk & 1;
    int tid  = threadIdx.x;
    int lane = tid & 31, head = tid >> 5;
    int gr = lane >> 2, lc = lane & 3;

    size_t hb = ((size_t)win * 8 + head) * 64 * 32;   // elems
    const uint32_t* q32 = (const uint32_t*)(g_q + hb);
    const uint32_t* k32 = (const uint32_t*)(g_k + hb);

    // stage V[64][32] of this head into smem (warp-local)
    {
        const bf16* vsrc = g_v + hb;
        #pragma unroll
        for (int it = 0; it < 8; it++) {
            int c = it * 32 + lane;       // 256 chunks of 16B
            int row = c >> 2, k8 = (c & 3) * 8;
            cp_async16(&vs[head][row][k8], vsrc + row * 32 + k8);
        }
        cp_commit();
    }

    // ---- S = Q K^T  (rows half*32..+31, cols 0..63) ----
    float sacc[2][8][4];
    #pragma unroll
    for (int mt = 0; mt < 2; mt++)
        #pragma unroll
        for (int nt = 0; nt < 8; nt++)
            #pragma unroll
            for (int e = 0; e < 4; e++) sacc[mt][nt][e] = 0.f;

    #pragma unroll
    for (int kt = 0; kt < 2; kt++) {
        uint32_t aQ[2][4];
        #pragma unroll
        for (int mt = 0; mt < 2; mt++) {
            int i0 = half * 32 + mt * 16 + gr;
            aQ[mt][0] = q32[i0 * 16 + 8 * kt + lc];
            aQ[mt][1] = q32[(i0 + 8) * 16 + 8 * kt + lc];
            aQ[mt][2] = q32[i0 * 16 + 8 * kt + lc + 4];
            aQ[mt][3] = q32[(i0 + 8) * 16 + 8 * kt + lc + 4];
        }
        uint32_t bK[8][2];
        #pragma unroll
        for (int nt = 0; nt < 8; nt++) {
            int j0 = nt * 8 + gr;
            bK[nt][0] = k32[j0 * 16 + 8 * kt + lc];
            bK[nt][1] = k32[j0 * 16 + 8 * kt + lc + 4];
        }
        #pragma unroll
        for (int mt = 0; mt < 2; mt++)
            #pragma unroll
            for (int nt = 0; nt < 8; nt++)
                mma_bf16(sacc[mt][nt], aQ[mt], bK[nt]);
    }

    // ---- bias + shifted-window mask per element ----
    int nw  = win & 63;
    int whb = (nw >> 3) * WSZ, wwb = (nw & 7) * WSZ;
    #pragma unroll
    for (int mt = 0; mt < 2; mt++) {
        #pragma unroll
        for (int re = 0; re < 2; re++) {
            int i = half * 32 + mt * 16 + gr + 8 * re;
            int ri = i >> 3, ci = i & 7;
            int yi = whb + ri, xi = wwb + ci;
            int labi = (yi < 56 ? 0 : (yi < 60 ? 1 : 2)) * 3 + (xi < 56 ? 0 : (xi < 60 ? 1 : 2));
            #pragma unroll
            for (int nt = 0; nt < 8; nt++) {
                #pragma unroll
                for (int e2 = 0; e2 < 2; e2++) {
                    int j = nt * 8 + 2 * lc + e2;
                    int rj = j >> 3, cj = j & 7;
                    int rel = (ri - rj + 7) * 15 + (ci - cj + 7);
                    float a = __ldg(&rpb[rel * 8 + head]);
                    int yj = whb + rj, xj = wwb + cj;
                    int labj = (yj < 56 ? 0 : (yj < 60 ? 1 : 2)) * 3 + (xj < 56 ? 0 : (xj < 60 ? 1 : 2));
                    if (labj != labi) a -= 100.f;
                    sacc[mt][nt][re * 2 + e2] += a;
                }
            }
        }
    }

    // ---- row softmax (exp unnormalized; normalize at epilogue) ----
    float inv[2][2];
    #pragma unroll
    for (int mt = 0; mt < 2; mt++) {
        #pragma unroll
        for (int re = 0; re < 2; re++) {
            float mx = -1e30f;
            #pragma unroll
            for (int nt = 0; nt < 8; nt++) {
                mx = fmaxf(mx, sacc[mt][nt][re * 2]);
                mx = fmaxf(mx, sacc[mt][nt][re * 2 + 1]);
            }
            mx = fmaxf(mx, __shfl_xor_sync(0xffffffffu, mx, 1));
            mx = fmaxf(mx, __shfl_xor_sync(0xffffffffu, mx, 2));
            float sm = 0.f;
            #pragma unroll
            for (int nt = 0; nt < 8; nt++) {
                float e0 = __expf(sacc[mt][nt][re * 2]     - mx);
                float e1 = __expf(sacc[mt][nt][re * 2 + 1] - mx);
                sacc[mt][nt][re * 2]     = e0;
                sacc[mt][nt][re * 2 + 1] = e1;
                sm += e0 + e1;
            }
            sm += __shfl_xor_sync(0xffffffffu, sm, 1);
            sm += __shfl_xor_sync(0xffffffffu, sm, 2);
            inv[mt][re] = 1.f / sm;
        }
    }

    // ---- O = P V ----
    cp_wait0();
    __syncwarp();

    uint32_t V0 = (uint32_t)__cvta_generic_to_shared(&vs[head][0][0]);
    int vmm = lane >> 3, vr8 = lane & 7;
    int vRow = (vmm & 1) * 8 + vr8, vNd = vmm >> 1;

    float oacc[2][4][4];
    #pragma unroll
    for (int mt = 0; mt < 2; mt++)
        #pragma unroll
        for (int nt = 0; nt < 4; nt++)
            #pragma unroll
            for (int e = 0; e < 4; e++) oacc[mt][nt][e] = 0.f;

    #pragma unroll
    for (int kt = 0; kt < 4; kt++) {
        uint32_t aP[2][4];
        #pragma unroll
        for (int mt = 0; mt < 2; mt++) {
            aP[mt][0] = pack_bf16(sacc[mt][2 * kt][0],     sacc[mt][2 * kt][1]);
            aP[mt][1] = pack_bf16(sacc[mt][2 * kt][2],     sacc[mt][2 * kt][3]);
            aP[mt][2] = pack_bf16(sacc[mt][2 * kt + 1][0], sacc[mt][2 * kt + 1][1]);
            aP[mt][3] = pack_bf16(sacc[mt][2 * kt + 1][2], sacc[mt][2 * kt + 1][3]);
        }
        uint32_t bV[4][2];
        #pragma unroll
        for (int p = 0; p < 2; p++) {
            uint32_t addr = V0 + (((16 * kt + vRow) * VST) + (p * 2 + vNd) * 8) * 2;
            ldsm4t(bV[2*p][0], bV[2*p][1], bV[2*p+1][0], bV[2*p+1][1], addr);
        }
        #pragma unroll
        for (int mt = 0; mt < 2; mt++)
            #pragma unroll
            for (int nt = 0; nt < 4; nt++)
                mma_bf16(oacc[mt][nt], aP[mt], bV[nt]);
    }

    // ---- epilogue: normalize, pack bf16, store ----
    uint32_t* ao32 = (uint32_t*)g_ao;
    #pragma unroll
    for (int mt = 0; mt < 2; mt++) {
        int i0 = half * 32 + mt * 16 + gr;
        float v0 = inv[mt][0], v1 = inv[mt][1];
        #pragma unroll
        for (int nt = 0; nt < 4; nt++) {
            uint32_t p0 = pack_bf16(oacc[mt][nt][0] * v0, oacc[mt][nt][1] * v0);
            uint32_t p1 = pack_bf16(oacc[mt][nt][2] * v1, oacc[mt][nt][3] * v1);
            size_t c = (size_t)head * 16 + nt * 4 + lc;
            ao32[((size_t)win * 64 + i0) * 128 + c]       = p0;
            ao32[((size_t)win * 64 + i0 + 8) * 128 + c]   = p1;
        }
    }
}

// ------------------------------- launcher ----------------------------------
extern "C" void kernel_launch(void* const* d_in, const int* in_sizes, int n_in,
                              void* d_out, int out_size)
{
    const float* x0   = (const float*)d_in[0];
    const float* x1   = (const float*)d_in[1];
    const float* g1_0 = (const float*)d_in[2];
    const float* b1_0 = (const float*)d_in[3];
    const float* g1_1 = (const float*)d_in[4];
    const float* b1_1 = (const float*)d_in[5];
    const float* Wq   = (const float*)d_in[6];
    const float* bq   = (const float*)d_in[7];
    const float* Wkv  = (const float*)d_in[8];
    const float* bkv  = (const float*)d_in[9];
    const float* rpb  = (const float*)d_in[10];
    const float* Wp   = (const float*)d_in[11];
    const float* bp   = (const float*)d_in[12];
    const float* g2   = (const float*)d_in[13];
    const float* b2   = (const float*)d_in[14];
    const float* Wfc1 = (const float*)d_in[15];
    const float* bfc1 = (const float*)d_in[16];
    const float* Wfc2 = (const float*)d_in[17];
    const float* bfc2 = (const float*)d_in[18];
    float* out = (float*)d_out;

    bf16 *bWq, *bWkv, *bWp, *bW1, *bW2;
    cudaGetSymbolAddress((void**)&bWq,  g_bWq);
    cudaGetSymbolAddress((void**)&bWkv, g_bWkv);
    cudaGetSymbolAddress((void**)&bWp,  g_bWp);
    cudaGetSymbolAddress((void**)&bW1,  g_bW1);
    cudaGetSymbolAddress((void**)&bW2,  g_bW2);

    convert_weights<<<dim3(128, 5), 256>>>(Wq, Wkv, Wp, Wfc1, Wfc2);
    ln_shift_part<<<dim3(MTOK, 2), 256>>>(x0, x1, g1_0, b1_0, g1_1, b1_1);
    mma_gemm<0><<<dim3(2, 512), 256>>>(bWq,  bq,   256,  nullptr, nullptr);
    mma_gemm<1><<<dim3(4, 512), 256>>>(bWkv, bkv,  256,  nullptr, nullptr);
    attn_kernel<<<2048, 256>>>(rpb);
    mma_gemm<2><<<dim3(2, 512), 256>>>(bWp,  bp,   256,  x1,      nullptr);
    ln_plain<<<MTOK, 256>>>(g2, b2);
    mma_gemm<3><<<dim3(8, 512), 256>>>(bW1,  bfc1, 256,  nullptr, nullptr);
    mma_gemm<4><<<dim3(2, 512), 256>>>(bW2,  bfc2, 1024, nullptr, out);
}

// round 4
// speedup vs baseline: 5.8027x; 1.5295x over previous
#include <cuda_runtime.h>
#include <cuda_bf16.h>
#include <cstdint>
#include <math.h>

#define DIMC   256
#define HEADS  8
#define WSZ    8
#define SHIFTW 4
#define BATCH  16
#define MTOK   (BATCH*64*64)         // 65536 tokens
#define QSCALE 0.17677669529663687f  // 32^-0.5

typedef __nv_bfloat16 bf16;

// -------- scratch (device globals) --------
__device__ bf16  g_x0w[MTOK*DIMC];
__device__ bf16  g_x1w[MTOK*DIMC];
__device__ bf16  g_q  [MTOK*DIMC];   // (win, head, n, d)
__device__ bf16  g_k  [MTOK*DIMC];
__device__ bf16  g_v  [MTOK*DIMC];
__device__ bf16  g_ao [MTOK*DIMC];   // attention out (win, n, dim)
__device__ float g_x  [MTOK*DIMC];   // residual stream (fp32)
__device__ bf16  g_xln[MTOK*DIMC];
__device__ bf16  g_h  [MTOK*4*DIMC];
__device__ bf16 g_bWq [DIMC*DIMC];
__device__ bf16 g_bWkv[2*DIMC*DIMC];
__device__ bf16 g_bWp [DIMC*DIMC];
__device__ bf16 g_bW1 [4*DIMC*DIMC];
__device__ bf16 g_bW2 [4*DIMC*DIMC];

// -------------------------- helpers ---------------------------------------
__device__ __forceinline__ void cp_async16(void* smem_dst, const void* gmem_src) {
    uint32_t s = (uint32_t)__cvta_generic_to_shared(smem_dst);
    asm volatile("cp.async.cg.shared.global [%0], [%1], 16;\n" :: "r"(s), "l"(gmem_src));
}
__device__ __forceinline__ void cp_commit() { asm volatile("cp.async.commit_group;\n"); }
__device__ __forceinline__ void cp_wait1()  { asm volatile("cp.async.wait_group 1;\n"); }
__device__ __forceinline__ void cp_wait0()  { asm volatile("cp.async.wait_group 0;\n"); }

__device__ __forceinline__ void mma_bf16(float c[4], const uint32_t a[4], const uint32_t b[2]) {
    asm volatile(
        "mma.sync.aligned.m16n8k16.row.col.f32.bf16.bf16.f32 "
        "{%0,%1,%2,%3}, {%4,%5,%6,%7}, {%8,%9}, {%0,%1,%2,%3};"
        : "+f"(c[0]), "+f"(c[1]), "+f"(c[2]), "+f"(c[3])
        : "r"(a[0]), "r"(a[1]), "r"(a[2]), "r"(a[3]), "r"(b[0]), "r"(b[1]));
}
__device__ __forceinline__ void ldsm4(uint32_t& r0, uint32_t& r1, uint32_t& r2, uint32_t& r3, uint32_t addr) {
    asm volatile("ldmatrix.sync.aligned.m8n8.x4.shared.b16 {%0,%1,%2,%3}, [%4];"
        : "=r"(r0), "=r"(r1), "=r"(r2), "=r"(r3) : "r"(addr));
}
__device__ __forceinline__ void ldsm4t(uint32_t& r0, uint32_t& r1, uint32_t& r2, uint32_t& r3, uint32_t addr) {
    asm volatile("ldmatrix.sync.aligned.m8n8.x4.trans.shared.b16 {%0,%1,%2,%3}, [%4];"
        : "=r"(r0), "=r"(r1), "=r"(r2), "=r"(r3) : "r"(addr));
}
__device__ __forceinline__ uint32_t pack_bf16(float lo, float hi) {
    uint32_t r;
    asm("cvt.rn.bf16x2.f32 %0, %1, %2;" : "=r"(r) : "f"(hi), "f"(lo));
    return r;
}
__device__ __forceinline__ float warp_sum(float v) {
    #pragma unroll
    for (int o = 16; o; o >>= 1) v += __shfl_xor_sync(0xffffffffu, v, o);
    return v;
}

// ---------------------- weight conversion fp32 -> bf16 ---------------------
__global__ void __launch_bounds__(256) convert_weights(
    const float* __restrict__ Wq, const float* __restrict__ Wkv,
    const float* __restrict__ Wp, const float* __restrict__ W1,
    const float* __restrict__ W2)
{
    int which = blockIdx.y;
    const float* src; bf16* dst; int n;
    if      (which == 0) { src = Wq;  dst = g_bWq;  n = DIMC*DIMC; }
    else if (which == 1) { src = Wkv; dst = g_bWkv; n = 2*DIMC*DIMC; }
    else if (which == 2) { src = Wp;  dst = g_bWp;  n = DIMC*DIMC; }
    else if (which == 3) { src = W1;  dst = g_bW1;  n = 4*DIMC*DIMC; }
    else                 { src = W2;  dst = g_bW2;  n = 4*DIMC*DIMC; }
    for (int i = blockIdx.x * 256 + threadIdx.x; i * 2 < n; i += gridDim.x * 256) {
        float2 v = ((const float2*)src)[i];
        ((uint32_t*)dst)[i] = pack_bf16(v.x, v.y);
    }
}

// ---------- LN + cyclic shift + window partition (warp per token) ----------
__global__ void __launch_bounds__(256) ln_shift_part(
    const float* __restrict__ x0, const float* __restrict__ x1,
    const float* __restrict__ g0, const float* __restrict__ b0,
    const float* __restrict__ g1, const float* __restrict__ b1)
{
    int warp = threadIdx.x >> 5, lane = threadIdx.x & 31;
    int outTok = blockIdx.x * 8 + warp;
    int which  = blockIdx.y;
    int win = outTok >> 6, n = outTok & 63;
    int b   = win >> 6,  nw = win & 63;
    int y = ((nw >> 3) * WSZ + (n >> 3) + SHIFTW) & 63;
    int x = ((nw & 7) * WSZ + (n & 7) + SHIFTW) & 63;
    const float4* src4 = (const float4*)((which ? x1 : x0) + (size_t)(b * 4096 + y * 64 + x) * DIMC);
    bf16* dst = (which ? g_x1w : g_x0w) + (size_t)outTok * DIMC;
    const float4* gg4 = (const float4*)(which ? g1 : g0);
    const float4* bb4 = (const float4*)(which ? b1 : b0);

    float4 v0 = src4[lane * 2], v1 = src4[lane * 2 + 1];
    float s = v0.x + v0.y + v0.z + v0.w + v1.x + v1.y + v1.z + v1.w;
    float mean = warp_sum(s) * (1.f / 256.f);
    float d0 = v0.x - mean, d1 = v0.y - mean, d2 = v0.z - mean, d3 = v0.w - mean;
    float d4 = v1.x - mean, d5 = v1.y - mean, d6 = v1.z - mean, d7 = v1.w - mean;
    float vv = d0*d0 + d1*d1 + d2*d2 + d3*d3 + d4*d4 + d5*d5 + d6*d6 + d7*d7;
    float r = rsqrtf(warp_sum(vv) * (1.f / 256.f) + 1e-5f);
    float4 ga = gg4[lane * 2], gb = gg4[lane * 2 + 1];
    float4 ba = bb4[lane * 2], bb = bb4[lane * 2 + 1];
    uint4 o;
    o.x = pack_bf16(d0 * r * ga.x + ba.x, d1 * r * ga.y + ba.y);
    o.y = pack_bf16(d2 * r * ga.z + ba.z, d3 * r * ga.w + ba.w);
    o.z = pack_bf16(d4 * r * gb.x + bb.x, d5 * r * gb.y + bb.y);
    o.w = pack_bf16(d6 * r * gb.z + bb.z, d7 * r * gb.w + bb.w);
    ((uint4*)dst)[lane] = o;
}

// ---------------- plain LN of g_x (fp32) -> g_xln (bf16), warp/token -------
__global__ void __launch_bounds__(256) ln_plain(
    const float* __restrict__ g2, const float* __restrict__ b2)
{
    int warp = threadIdx.x >> 5, lane = threadIdx.x & 31;
    size_t tok = (size_t)blockIdx.x * 8 + warp;
    const float4* src4 = (const float4*)(g_x + tok * DIMC);
    bf16* dst = g_xln + tok * DIMC;
    const float4* gg4 = (const float4*)g2;
    const float4* bb4 = (const float4*)b2;

    float4 v0 = src4[lane * 2], v1 = src4[lane * 2 + 1];
    float s = v0.x + v0.y + v0.z + v0.w + v1.x + v1.y + v1.z + v1.w;
    float mean = warp_sum(s) * (1.f / 256.f);
    float d0 = v0.x - mean, d1 = v0.y - mean, d2 = v0.z - mean, d3 = v0.w - mean;
    float d4 = v1.x - mean, d5 = v1.y - mean, d6 = v1.z - mean, d7 = v1.w - mean;
    float vv = d0*d0 + d1*d1 + d2*d2 + d3*d3 + d4*d4 + d5*d5 + d6*d6 + d7*d7;
    float r = rsqrtf(warp_sum(vv) * (1.f / 256.f) + 1e-5f);
    float4 ga = gg4[lane * 2], gb = gg4[lane * 2 + 1];
    float4 ba = bb4[lane * 2], bb = bb4[lane * 2 + 1];
    uint4 o;
    o.x = pack_bf16(d0 * r * ga.x + ba.x, d1 * r * ga.y + ba.y);
    o.y = pack_bf16(d2 * r * ga.z + ba.z, d3 * r * ga.w + ba.w);
    o.z = pack_bf16(d4 * r * gb.x + bb.x, d5 * r * gb.y + bb.y);
    o.w = pack_bf16(d6 * r * gb.z + bb.z, d7 * r * gb.w + bb.w);
    ((uint4*)dst)[lane] = o;
}

// ----------------------- bf16 tensor-core GEMMs ----------------------------
#define BK 32
#define SST 40

template<int MODE>
__device__ __forceinline__ void emit_pair(int m, int c0, float v0, float v1,
    const float* __restrict__ bias, const float* __restrict__ extra,
    float* __restrict__ out)
{
    v0 += __ldg(&bias[c0]);
    v1 += __ldg(&bias[c0 + 1]);
    if (MODE == 0) {
        v0 *= QSCALE; v1 *= QSCALE;
        int win = m >> 6, n = m & 63, hd = c0 >> 5, d = c0 & 31;
        uint32_t* p = (uint32_t*)g_q + ((((size_t)win * 8 + hd) * 64 + n) * 32 + d) / 2;
        *p = pack_bf16(v0, v1);
    } else if (MODE == 1) {
        int win = m >> 6, n = m & 63;
        int c2 = c0 & 255, hd = c2 >> 5, d = c2 & 31;
        size_t idx = ((((size_t)win * 8 + hd) * 64 + n) * 32 + d) / 2;
        uint32_t* p = (c0 < 256 ? (uint32_t*)g_k : (uint32_t*)g_v) + idx;
        *p = pack_bf16(v0, v1);
    } else if (MODE == 2) {
        int win = m >> 6, n = m & 63;
        int b = win >> 6, nw = win & 63;
        int y = ((nw >> 3) * WSZ + (n >> 3) + SHIFTW) & 63;
        int x = ((nw & 7) * WSZ + (n & 7) + SHIFTW) & 63;
        size_t t = ((size_t)(b * 4096 + y * 64 + x)) * DIMC + c0;
        float2 e = *(const float2*)&extra[t];
        *(float2*)&g_x[t] = make_float2(e.x + v0, e.y + v1);
    } else if (MODE == 3) {
        v0 = 0.5f * v0 * (1.f + erff(v0 * 0.70710678118654752f));
        v1 = 0.5f * v1 * (1.f + erff(v1 * 0.70710678118654752f));
        *((uint32_t*)g_h + ((size_t)m * 1024 + c0) / 2) = pack_bf16(v0, v1);
    } else {
        size_t t = (size_t)m * DIMC + c0;
        float2 r = *(const float2*)&g_x[t];
        *(float2*)&out[t] = make_float2(r.x + v0, r.y + v1);
    }
}

template<int MODE>
__global__ void __launch_bounds__(256, 2) mma_gemm(
    const bf16* __restrict__ W, const float* __restrict__ bias,
    int K, const float* __restrict__ extra, float* __restrict__ out)
{
    const bf16* A = (MODE == 0) ? g_x1w :
                    (MODE == 1) ? g_x0w :
                    (MODE == 2) ? g_ao  :
                    (MODE == 3) ? g_xln : g_h;

    __shared__ bf16 As[2][128][SST];
    __shared__ bf16 Ws[2][128][SST];

    int tid  = threadIdx.x;
    int lane = tid & 31, warp = tid >> 5;
    int gr = lane >> 2, lc = lane & 3;
    int mWarp = (warp >> 2) * 64;
    int nWarp = (warp & 3) * 32;
    int rowBase = blockIdx.y * 128;
    int colBase = blockIdx.x * 128;

    int lr = tid >> 2;
    int lk8 = (tid & 3) * 8;
    const bf16* Abase = A + (size_t)rowBase * K + lk8;
    const bf16* Wbase = W + (size_t)colBase * K + lk8;

    int mm = lane >> 3, r8 = lane & 7;
    int aRow = (mm & 1) * 8 + r8, aK = (mm >> 1) * 8;
    int bRow = (mm >> 1) * 8 + r8, bKo = (mm & 1) * 8;
    uint32_t A0 = (uint32_t)__cvta_generic_to_shared(&As[0][0][0]);
    uint32_t W0 = (uint32_t)__cvta_generic_to_shared(&Ws[0][0][0]);
    uint32_t aAddr = A0 + ((mWarp + aRow) * SST + aK) * 2;
    uint32_t bAddr = W0 + ((nWarp + bRow) * SST + bKo) * 2;
    const uint32_t BUFSZ = 128 * SST * 2;

    float acc[4][4][4];
    #pragma unroll
    for (int mi = 0; mi < 4; mi++)
        #pragma unroll
        for (int ni = 0; ni < 4; ni++)
            #pragma unroll
            for (int e = 0; e < 4; e++) acc[mi][ni][e] = 0.f;

    int nK = K / BK;

    cp_async16(&As[0][lr][lk8],      Abase + (size_t)lr * K);
    cp_async16(&As[0][lr + 64][lk8], Abase + (size_t)(lr + 64) * K);
    cp_async16(&Ws[0][lr][lk8],      Wbase + (size_t)lr * K);
    cp_async16(&Ws[0][lr + 64][lk8], Wbase + (size_t)(lr + 64) * K);
    cp_commit();

    for (int s = 0; s < nK; ++s) {
        if (s + 1 < nK) {
            int nb = (s + 1) & 1;
            size_t koff = (size_t)(s + 1) * BK;
            cp_async16(&As[nb][lr][lk8],      Abase + (size_t)lr * K + koff);
            cp_async16(&As[nb][lr + 64][lk8], Abase + (size_t)(lr + 64) * K + koff);
            cp_async16(&Ws[nb][lr][lk8],      Wbase + (size_t)lr * K + koff);
            cp_async16(&Ws[nb][lr + 64][lk8], Wbase + (size_t)(lr + 64) * K + koff);
            cp_commit();
            cp_wait1();
        } else {
            cp_wait0();
        }
        __syncthreads();

        uint32_t bufOff = (s & 1) ? BUFSZ : 0;
        #pragma unroll
        for (int ks = 0; ks < 2; ++ks) {
            int kb = ks * 16;
            uint32_t aF[4][4], bF[4][2];
            #pragma unroll
            for (int mi = 0; mi < 4; mi++)
                ldsm4(aF[mi][0], aF[mi][1], aF[mi][2], aF[mi][3],
                      aAddr + bufOff + (mi * 16 * SST + kb) * 2);
            ldsm4(bF[0][0], bF[0][1], bF[1][0], bF[1][1], bAddr + bufOff + kb * 2);
            ldsm4(bF[2][0], bF[2][1], bF[3][0], bF[3][1], bAddr + bufOff + (16 * SST + kb) * 2);
            #pragma unroll
            for (int mi = 0; mi < 4; mi++)
                #pragma unroll
                for (int ni = 0; ni < 4; ni++)
                    mma_bf16(acc[mi][ni], aF[mi], bF[ni]);
        }
        __syncthreads();
    }

    #pragma unroll
    for (int mi = 0; mi < 4; mi++) {
        int r0 = rowBase + mWarp + mi * 16 + gr;
        #pragma unroll
        for (int ni = 0; ni < 4; ni++) {
            int c0 = colBase + nWarp + ni * 8 + lc * 2;
            emit_pair<MODE>(r0,     c0, acc[mi][ni][0], acc[mi][ni][1], bias, extra, out);
            emit_pair<MODE>(r0 + 8, c0, acc[mi][ni][2], acc[mi][ni][3], bias, extra, out);
        }
    }
}

// ------------- tensor-core attention: warp = (head, row-half) --------------
#define VST 40
__global__ void __launch_bounds__(256) attn_kernel(const float* __restrict__ rpb)
{
    __shared__ bf16 vs[8][64][VST];

    int blk  = blockIdx.x;
    int win  = blk >> 1, half = blk & 1;
    int tid  = threadIdx.x;
    int lane = tid & 31, head = tid >> 5;
    int gr = lane >> 2, lc = lane & 3;

    size_t hb = ((size_t)win * 8 + head) * 64 * 32;
    const uint32_t* q32 = (const uint32_t*)(g_q + hb);
    const uint32_t* k32 = (const uint32_t*)(g_k + hb);

    {
        const bf16* vsrc = g_v + hb;
        #pragma unroll
        for (int it = 0; it < 8; it++) {
            int c = it * 32 + lane;
            int row = c >> 2, k8 = (c & 3) * 8;
            cp_async16(&vs[head][row][k8], vsrc + row * 32 + k8);
        }
        cp_commit();
    }

    float sacc[2][8][4];
    #pragma unroll
    for (int mt = 0; mt < 2; mt++)
        #pragma unroll
        for (int nt = 0; nt < 8; nt++)
            #pragma unroll
            for (int e = 0; e < 4; e++) sacc[mt][nt][e] = 0.f;

    #pragma unroll
    for (int kt = 0; kt < 2; kt++) {
        uint32_t aQ[2][4];
        #pragma unroll
        for (int mt = 0; mt < 2; mt++) {
            int i0 = half * 32 + mt * 16 + gr;
            aQ[mt][0] = q32[i0 * 16 + 8 * kt + lc];
            aQ[mt][1] = q32[(i0 + 8) * 16 + 8 * kt + lc];
            aQ[mt][2] = q32[i0 * 16 + 8 * kt + lc + 4];
            aQ[mt][3] = q32[(i0 + 8) * 16 + 8 * kt + lc + 4];
        }
        uint32_t bK[8][2];
        #pragma unroll
        for (int nt = 0; nt < 8; nt++) {
            int j0 = nt * 8 + gr;
            bK[nt][0] = k32[j0 * 16 + 8 * kt + lc];
            bK[nt][1] = k32[j0 * 16 + 8 * kt + lc + 4];
        }
        #pragma unroll
        for (int mt = 0; mt < 2; mt++)
            #pragma unroll
            for (int nt = 0; nt < 8; nt++)
                mma_bf16(sacc[mt][nt], aQ[mt], bK[nt]);
    }

    int nw  = win & 63;
    int whb = (nw >> 3) * WSZ, wwb = (nw & 7) * WSZ;
    #pragma unroll
    for (int mt = 0; mt < 2; mt++) {
        #pragma unroll
        for (int re = 0; re < 2; re++) {
            int i = half * 32 + mt * 16 + gr + 8 * re;
            int ri = i >> 3, ci = i & 7;
            int yi = whb + ri, xi = wwb + ci;
            int labi = (yi < 56 ? 0 : (yi < 60 ? 1 : 2)) * 3 + (xi < 56 ? 0 : (xi < 60 ? 1 : 2));
            #pragma unroll
            for (int nt = 0; nt < 8; nt++) {
                #pragma unroll
                for (int e2 = 0; e2 < 2; e2++) {
                    int j = nt * 8 + 2 * lc + e2;
                    int rj = j >> 3, cj = j & 7;
                    int rel = (ri - rj + 7) * 15 + (ci - cj + 7);
                    float a = __ldg(&rpb[rel * 8 + head]);
                    int yj = whb + rj, xj = wwb + cj;
                    int labj = (yj < 56 ? 0 : (yj < 60 ? 1 : 2)) * 3 + (xj < 56 ? 0 : (xj < 60 ? 1 : 2));
                    if (labj != labi) a -= 100.f;
                    sacc[mt][nt][re * 2 + e2] += a;
                }
            }
        }
    }

    float inv[2][2];
    #pragma unroll
    for (int mt = 0; mt < 2; mt++) {
        #pragma unroll
        for (int re = 0; re < 2; re++) {
            float mx = -1e30f;
            #pragma unroll
            for (int nt = 0; nt < 8; nt++) {
                mx = fmaxf(mx, sacc[mt][nt][re * 2]);
                mx = fmaxf(mx, sacc[mt][nt][re * 2 + 1]);
            }
            mx = fmaxf(mx, __shfl_xor_sync(0xffffffffu, mx, 1));
            mx = fmaxf(mx, __shfl_xor_sync(0xffffffffu, mx, 2));
            float sm = 0.f;
            #pragma unroll
            for (int nt = 0; nt < 8; nt++) {
                float e0 = __expf(sacc[mt][nt][re * 2]     - mx);
                float e1 = __expf(sacc[mt][nt][re * 2 + 1] - mx);
                sacc[mt][nt][re * 2]     = e0;
                sacc[mt][nt][re * 2 + 1] = e1;
                sm += e0 + e1;
            }
            sm += __shfl_xor_sync(0xffffffffu, sm, 1);
            sm += __shfl_xor_sync(0xffffffffu, sm, 2);
            inv[mt][re] = 1.f / sm;
        }
    }

    cp_wait0();
    __syncwarp();

    uint32_t V0 = (uint32_t)__cvta_generic_to_shared(&vs[head][0][0]);
    int vmm = lane >> 3, vr8 = lane & 7;
    int vRow = (vmm & 1) * 8 + vr8, vNd = vmm >> 1;

    float oacc[2][4][4];
    #pragma unroll
    for (int mt = 0; mt < 2; mt++)
        #pragma unroll
        for (int nt = 0; nt < 4; nt++)
            #pragma unroll
            for (int e = 0; e < 4; e++) oacc[mt][nt][e] = 0.f;

    #pragma unroll
    for (int kt = 0; kt < 4; kt++) {
        uint32_t aP[2][4];
        #pragma unroll
        for (int mt = 0; mt < 2; mt++) {
            aP[mt][0] = pack_bf16(sacc[mt][2 * kt][0],     sacc[mt][2 * kt][1]);
            aP[mt][1] = pack_bf16(sacc[mt][2 * kt][2],     sacc[mt][2 * kt][3]);
            aP[mt][2] = pack_bf16(sacc[mt][2 * kt + 1][0], sacc[mt][2 * kt + 1][1]);
            aP[mt][3] = pack_bf16(sacc[mt][2 * kt + 1][2], sacc[mt][2 * kt + 1][3]);
        }
        uint32_t bV[4][2];
        #pragma unroll
        for (int p = 0; p < 2; p++) {
            uint32_t addr = V0 + (((16 * kt + vRow) * VST) + (p * 2 + vNd) * 8) * 2;
            ldsm4t(bV[2*p][0], bV[2*p][1], bV[2*p+1][0], bV[2*p+1][1], addr);
        }
        #pragma unroll
        for (int mt = 0; mt < 2; mt++)
            #pragma unroll
            for (int nt = 0; nt < 4; nt++)
                mma_bf16(oacc[mt][nt], aP[mt], bV[nt]);
    }

    uint32_t* ao32 = (uint32_t*)g_ao;
    #pragma unroll
    for (int mt = 0; mt < 2; mt++) {
        int i0 = half * 32 + mt * 16 + gr;
        float v0 = inv[mt][0], v1 = inv[mt][1];
        #pragma unroll
        for (int nt = 0; nt < 4; nt++) {
            uint32_t p0 = pack_bf16(oacc[mt][nt][0] * v0, oacc[mt][nt][1] * v0);
            uint32_t p1 = pack_bf16(oacc[mt][nt][2] * v1, oacc[mt][nt][3] * v1);
            size_t c = (size_t)head * 16 + nt * 4 + lc;
            ao32[((size_t)win * 64 + i0) * 128 + c]     = p0;
            ao32[((size_t)win * 64 + i0 + 8) * 128 + c] = p1;
        }
    }
}

// ------------------------------- launcher ----------------------------------
extern "C" void kernel_launch(void* const* d_in, const int* in_sizes, int n_in,
                              void* d_out, int out_size)
{
    const float* x0   = (const float*)d_in[0];
    const float* x1   = (const float*)d_in[1];
    const float* g1_0 = (const float*)d_in[2];
    const float* b1_0 = (const float*)d_in[3];
    const float* g1_1 = (const float*)d_in[4];
    const float* b1_1 = (const float*)d_in[5];
    const float* Wq   = (const float*)d_in[6];
    const float* bq   = (const float*)d_in[7];
    const float* Wkv  = (const float*)d_in[8];
    const float* bkv  = (const float*)d_in[9];
    const float* rpb  = (const float*)d_in[10];
    const float* Wp   = (const float*)d_in[11];
    const float* bp   = (const float*)d_in[12];
    const float* g2   = (const float*)d_in[13];
    const float* b2   = (const float*)d_in[14];
    const float* Wfc1 = (const float*)d_in[15];
    const float* bfc1 = (const float*)d_in[16];
    const float* Wfc2 = (const float*)d_in[17];
    const float* bfc2 = (const float*)d_in[18];
    float* out = (float*)d_out;

    bf16 *bWq, *bWkv, *bWp, *bW1, *bW2;
    cudaGetSymbolAddress((void**)&bWq,  g_bWq);
    cudaGetSymbolAddress((void**)&bWkv, g_bWkv);
    cudaGetSymbolAddress((void**)&bWp,  g_bWp);
    cudaGetSymbolAddress((void**)&bW1,  g_bW1);
    cudaGetSymbolAddress((void**)&bW2,  g_bW2);

    convert_weights<<<dim3(128, 5), 256>>>(Wq, Wkv, Wp, Wfc1, Wfc2);
    ln_shift_part<<<dim3(MTOK / 8, 2), 256>>>(x0, x1, g1_0, b1_0, g1_1, b1_1);
    mma_gemm<0><<<dim3(2, 512), 256>>>(bWq,  bq,   256,  nullptr, nullptr);
    mma_gemm<1><<<dim3(4, 512), 256>>>(bWkv, bkv,  256,  nullptr, nullptr);
    attn_kernel<<<2048, 256>>>(rpb);
    mma_gemm<2><<<dim3(2, 512), 256>>>(bWp,  bp,   256,  x1,      nullptr);
    ln_plain<<<MTOK / 8, 256>>>(g2, b2);
    mma_gemm<3><<<dim3(8, 512), 256>>>(bW1,  bfc1, 256,  nullptr, nullptr);
    mma_gemm<4><<<dim3(2, 512), 256>>>(bW2,  bfc2, 1024, nullptr, out);
}

// round 5
// speedup vs baseline: 6.1680x; 1.0629x over previous
#include <cuda_runtime.h>
#include <cuda_bf16.h>
#include <cstdint>
#include <math.h>

#define DIMC   256
#define HEADS  8
#define WSZ    8
#define SHIFTW 4
#define BATCH  16
#define MTOK   (BATCH*64*64)         // 65536 tokens
#define QSCALE 0.17677669529663687f  // 32^-0.5

typedef __nv_bfloat16 bf16;

// -------- scratch (device globals) --------
__device__ bf16  g_x0w[MTOK*DIMC];
__device__ bf16  g_x1w[MTOK*DIMC];
__device__ bf16  g_q  [MTOK*DIMC];   // (win, head, n, d)
__device__ bf16  g_k  [MTOK*DIMC];
__device__ bf16  g_v  [MTOK*DIMC];
__device__ bf16  g_ao [MTOK*DIMC];   // attention out (win, n, dim)
__device__ float g_x  [MTOK*DIMC];   // residual stream (fp32)
__device__ bf16  g_xln[MTOK*DIMC];
__device__ bf16  g_h  [MTOK*4*DIMC];
__device__ bf16 g_bWq [DIMC*DIMC];
__device__ bf16 g_bWkv[2*DIMC*DIMC];
__device__ bf16 g_bWp [DIMC*DIMC];
__device__ bf16 g_bW1 [4*DIMC*DIMC];
__device__ bf16 g_bW2 [4*DIMC*DIMC];

// -------------------------- helpers ---------------------------------------
__device__ __forceinline__ void cp_async16(void* smem_dst, const void* gmem_src) {
    uint32_t s = (uint32_t)__cvta_generic_to_shared(smem_dst);
    asm volatile("cp.async.cg.shared.global [%0], [%1], 16;\n" :: "r"(s), "l"(gmem_src));
}
__device__ __forceinline__ void cp_commit() { asm volatile("cp.async.commit_group;\n"); }
__device__ __forceinline__ void cp_wait1()  { asm volatile("cp.async.wait_group 1;\n"); }
__device__ __forceinline__ void cp_wait0()  { asm volatile("cp.async.wait_group 0;\n"); }

__device__ __forceinline__ void mma_bf16(float c[4], const uint32_t a[4], const uint32_t b[2]) {
    asm volatile(
        "mma.sync.aligned.m16n8k16.row.col.f32.bf16.bf16.f32 "
        "{%0,%1,%2,%3}, {%4,%5,%6,%7}, {%8,%9}, {%0,%1,%2,%3};"
        : "+f"(c[0]), "+f"(c[1]), "+f"(c[2]), "+f"(c[3])
        : "r"(a[0]), "r"(a[1]), "r"(a[2]), "r"(a[3]), "r"(b[0]), "r"(b[1]));
}
__device__ __forceinline__ void ldsm4(uint32_t& r0, uint32_t& r1, uint32_t& r2, uint32_t& r3, uint32_t addr) {
    asm volatile("ldmatrix.sync.aligned.m8n8.x4.shared.b16 {%0,%1,%2,%3}, [%4];"
        : "=r"(r0), "=r"(r1), "=r"(r2), "=r"(r3) : "r"(addr));
}
__device__ __forceinline__ void ldsm4t(uint32_t& r0, uint32_t& r1, uint32_t& r2, uint32_t& r3, uint32_t addr) {
    asm volatile("ldmatrix.sync.aligned.m8n8.x4.trans.shared.b16 {%0,%1,%2,%3}, [%4];"
        : "=r"(r0), "=r"(r1), "=r"(r2), "=r"(r3) : "r"(addr));
}
__device__ __forceinline__ uint32_t pack_bf16(float lo, float hi) {
    uint32_t r;
    asm("cvt.rn.bf16x2.f32 %0, %1, %2;" : "=r"(r) : "f"(hi), "f"(lo));
    return r;
}
__device__ __forceinline__ float warp_sum(float v) {
    #pragma unroll
    for (int o = 16; o; o >>= 1) v += __shfl_xor_sync(0xffffffffu, v, o);
    return v;
}

// ---------------------- weight conversion fp32 -> bf16 ---------------------
__global__ void __launch_bounds__(256) convert_weights(
    const float* __restrict__ Wq, const float* __restrict__ Wkv,
    const float* __restrict__ Wp, const float* __restrict__ W1,
    const float* __restrict__ W2)
{
    int which = blockIdx.y;
    const float* src; bf16* dst; int n;
    if      (which == 0) { src = Wq;  dst = g_bWq;  n = DIMC*DIMC; }
    else if (which == 1) { src = Wkv; dst = g_bWkv; n = 2*DIMC*DIMC; }
    else if (which == 2) { src = Wp;  dst = g_bWp;  n = DIMC*DIMC; }
    else if (which == 3) { src = W1;  dst = g_bW1;  n = 4*DIMC*DIMC; }
    else                 { src = W2;  dst = g_bW2;  n = 4*DIMC*DIMC; }
    for (int i = blockIdx.x * 256 + threadIdx.x; i * 4 < n; i += gridDim.x * 256) {
        float4 v = ((const float4*)src)[i];
        uint2 o;
        o.x = pack_bf16(v.x, v.y);
        o.y = pack_bf16(v.z, v.w);
        ((uint2*)dst)[i] = o;
    }
}

// ---------- LN + cyclic shift + window partition (warp per token) ----------
__global__ void __launch_bounds__(256) ln_shift_part(
    const float* __restrict__ x0, const float* __restrict__ x1,
    const float* __restrict__ g0, const float* __restrict__ b0,
    const float* __restrict__ g1, const float* __restrict__ b1)
{
    int warp = threadIdx.x >> 5, lane = threadIdx.x & 31;
    int outTok = blockIdx.x * 8 + warp;
    int which  = blockIdx.y;
    int win = outTok >> 6, n = outTok & 63;
    int b   = win >> 6,  nw = win & 63;
    int y = ((nw >> 3) * WSZ + (n >> 3) + SHIFTW) & 63;
    int x = ((nw & 7) * WSZ + (n & 7) + SHIFTW) & 63;
    const float4* src4 = (const float4*)((which ? x1 : x0) + (size_t)(b * 4096 + y * 64 + x) * DIMC);
    bf16* dst = (which ? g_x1w : g_x0w) + (size_t)outTok * DIMC;
    const float4* gg4 = (const float4*)(which ? g1 : g0);
    const float4* bb4 = (const float4*)(which ? b1 : b0);

    float4 v0 = src4[lane * 2], v1 = src4[lane * 2 + 1];
    float s = v0.x + v0.y + v0.z + v0.w + v1.x + v1.y + v1.z + v1.w;
    float mean = warp_sum(s) * (1.f / 256.f);
    float d0 = v0.x - mean, d1 = v0.y - mean, d2 = v0.z - mean, d3 = v0.w - mean;
    float d4 = v1.x - mean, d5 = v1.y - mean, d6 = v1.z - mean, d7 = v1.w - mean;
    float vv = d0*d0 + d1*d1 + d2*d2 + d3*d3 + d4*d4 + d5*d5 + d6*d6 + d7*d7;
    float r = rsqrtf(warp_sum(vv) * (1.f / 256.f) + 1e-5f);
    float4 ga = gg4[lane * 2], gb = gg4[lane * 2 + 1];
    float4 ba = bb4[lane * 2], bb = bb4[lane * 2 + 1];
    uint4 o;
    o.x = pack_bf16(d0 * r * ga.x + ba.x, d1 * r * ga.y + ba.y);
    o.y = pack_bf16(d2 * r * ga.z + ba.z, d3 * r * ga.w + ba.w);
    o.z = pack_bf16(d4 * r * gb.x + bb.x, d5 * r * gb.y + bb.y);
    o.w = pack_bf16(d6 * r * gb.z + bb.z, d7 * r * gb.w + bb.w);
    ((uint4*)dst)[lane] = o;
}

// ---------------- plain LN of g_x (fp32) -> g_xln (bf16), warp/token -------
__global__ void __launch_bounds__(256) ln_plain(
    const float* __restrict__ g2, const float* __restrict__ b2)
{
    int warp = threadIdx.x >> 5, lane = threadIdx.x & 31;
    size_t tok = (size_t)blockIdx.x * 8 + warp;
    const float4* src4 = (const float4*)(g_x + tok * DIMC);
    bf16* dst = g_xln + tok * DIMC;
    const float4* gg4 = (const float4*)g2;
    const float4* bb4 = (const float4*)b2;

    float4 v0 = src4[lane * 2], v1 = src4[lane * 2 + 1];
    float s = v0.x + v0.y + v0.z + v0.w + v1.x + v1.y + v1.z + v1.w;
    float mean = warp_sum(s) * (1.f / 256.f);
    float d0 = v0.x - mean, d1 = v0.y - mean, d2 = v0.z - mean, d3 = v0.w - mean;
    float d4 = v1.x - mean, d5 = v1.y - mean, d6 = v1.z - mean, d7 = v1.w - mean;
    float vv = d0*d0 + d1*d1 + d2*d2 + d3*d3 + d4*d4 + d5*d5 + d6*d6 + d7*d7;
    float r = rsqrtf(warp_sum(vv) * (1.f / 256.f) + 1e-5f);
    float4 ga = gg4[lane * 2], gb = gg4[lane * 2 + 1];
    float4 ba = bb4[lane * 2], bb = bb4[lane * 2 + 1];
    uint4 o;
    o.x = pack_bf16(d0 * r * ga.x + ba.x, d1 * r * ga.y + ba.y);
    o.y = pack_bf16(d2 * r * ga.z + ba.z, d3 * r * ga.w + ba.w);
    o.z = pack_bf16(d4 * r * gb.x + bb.x, d5 * r * gb.y + bb.y);
    o.w = pack_bf16(d6 * r * gb.z + bb.z, d7 * r * gb.w + bb.w);
    ((uint4*)dst)[lane] = o;
}

// ----------------------- bf16 tensor-core GEMMs ----------------------------
// 128x128 tile, BK=32, 3-stage cp.async ring, ONE __syncthreads per k-iter.
#define BK 32
#define SST 40
#define NSTAGE 3
#define AR_ELEMS (128*SST)          // elems per operand per stage
#define STAGE_BYTES (AR_ELEMS*2*2)  // A+W, bf16
#define GEMM_SMEM (NSTAGE*STAGE_BYTES)

template<int MODE>
__device__ __forceinline__ void emit_pair(int m, int c0, float v0, float v1,
    const float* __restrict__ bias, const float* __restrict__ extra,
    float* __restrict__ out)
{
    v0 += __ldg(&bias[c0]);
    v1 += __ldg(&bias[c0 + 1]);
    if (MODE == 0) {
        v0 *= QSCALE; v1 *= QSCALE;
        int win = m >> 6, n = m & 63, hd = c0 >> 5, d = c0 & 31;
        uint32_t* p = (uint32_t*)g_q + ((((size_t)win * 8 + hd) * 64 + n) * 32 + d) / 2;
        *p = pack_bf16(v0, v1);
    } else if (MODE == 1) {
        int win = m >> 6, n = m & 63;
        int c2 = c0 & 255, hd = c2 >> 5, d = c2 & 31;
        size_t idx = ((((size_t)win * 8 + hd) * 64 + n) * 32 + d) / 2;
        uint32_t* p = (c0 < 256 ? (uint32_t*)g_k : (uint32_t*)g_v) + idx;
        *p = pack_bf16(v0, v1);
    } else if (MODE == 2) {
        int win = m >> 6, n = m & 63;
        int b = win >> 6, nw = win & 63;
        int y = ((nw >> 3) * WSZ + (n >> 3) + SHIFTW) & 63;
        int x = ((nw & 7) * WSZ + (n & 7) + SHIFTW) & 63;
        size_t t = ((size_t)(b * 4096 + y * 64 + x)) * DIMC + c0;
        float2 e = *(const float2*)&extra[t];
        *(float2*)&g_x[t] = make_float2(e.x + v0, e.y + v1);
    } else if (MODE == 3) {
        v0 = 0.5f * v0 * (1.f + erff(v0 * 0.70710678118654752f));
        v1 = 0.5f * v1 * (1.f + erff(v1 * 0.70710678118654752f));
        *((uint32_t*)g_h + ((size_t)m * 1024 + c0) / 2) = pack_bf16(v0, v1);
    } else {
        size_t t = (size_t)m * DIMC + c0;
        float2 r = *(const float2*)&g_x[t];
        *(float2*)&out[t] = make_float2(r.x + v0, r.y + v1);
    }
}

template<int MODE>
__global__ void __launch_bounds__(256, 2) mma_gemm(
    const bf16* __restrict__ W, const float* __restrict__ bias,
    int K, const float* __restrict__ extra, float* __restrict__ out)
{
    extern __shared__ bf16 sm[];
    const bf16* A = (MODE == 0) ? g_x1w :
                    (MODE == 1) ? g_x0w :
                    (MODE == 2) ? g_ao  :
                    (MODE == 3) ? g_xln : g_h;

    int tid  = threadIdx.x;
    int lane = tid & 31, warp = tid >> 5;
    int gr = lane >> 2, lc = lane & 3;
    int mWarp = (warp >> 2) * 64;
    int nWarp = (warp & 3) * 32;
    int rowBase = blockIdx.y * 128;
    int colBase = blockIdx.x * 128;

    int lr = tid >> 2;
    int lk8 = (tid & 3) * 8;
    const bf16* Abase = A + (size_t)rowBase * K + lk8;
    const bf16* Wbase = W + (size_t)colBase * K + lk8;

    int mm = lane >> 3, r8 = lane & 7;
    int aRow = (mm & 1) * 8 + r8, aK = (mm >> 1) * 8;
    int bRow = (mm >> 1) * 8 + r8, bKo = (mm & 1) * 8;
    uint32_t Sbase = (uint32_t)__cvta_generic_to_shared(sm);
    uint32_t aAddr = Sbase + ((mWarp + aRow) * SST + aK) * 2;
    uint32_t bAddr = Sbase + AR_ELEMS * 2 + ((nWarp + bRow) * SST + bKo) * 2;

    float acc[4][4][4];
    #pragma unroll
    for (int mi = 0; mi < 4; mi++)
        #pragma unroll
        for (int ni = 0; ni < 4; ni++)
            #pragma unroll
            for (int e = 0; e < 4; e++) acc[mi][ni][e] = 0.f;

    int nK = K / BK;

    // prefetch stages 0,1
    #pragma unroll
    for (int st = 0; st < NSTAGE - 1; st++) {
        size_t koff = (size_t)st * BK;
        bf16* dA = sm + st * 2 * AR_ELEMS;
        bf16* dW = dA + AR_ELEMS;
        cp_async16(dA + lr * SST + lk8,        Abase + (size_t)lr * K + koff);
        cp_async16(dA + (lr + 64) * SST + lk8, Abase + (size_t)(lr + 64) * K + koff);
        cp_async16(dW + lr * SST + lk8,        Wbase + (size_t)lr * K + koff);
        cp_async16(dW + (lr + 64) * SST + lk8, Wbase + (size_t)(lr + 64) * K + koff);
        cp_commit();
    }

    int stComp = 0, stPf = NSTAGE - 1;
    for (int s = 0; s < nK; ++s) {
        cp_wait1();               // stage s landed
        __syncthreads();          // ONE barrier per iteration

        int pf = s + NSTAGE - 1;
        if (pf < nK) {
            size_t koff = (size_t)pf * BK;
            bf16* dA = sm + stPf * 2 * AR_ELEMS;
            bf16* dW = dA + AR_ELEMS;
            cp_async16(dA + lr * SST + lk8,        Abase + (size_t)lr * K + koff);
            cp_async16(dA + (lr + 64) * SST + lk8, Abase + (size_t)(lr + 64) * K + koff);
            cp_async16(dW + lr * SST + lk8,        Wbase + (size_t)lr * K + koff);
            cp_async16(dW + (lr + 64) * SST + lk8, Wbase + (size_t)(lr + 64) * K + koff);
        }
        cp_commit();              // commit (possibly empty) to keep group math uniform
        if (++stPf == NSTAGE) stPf = 0;

        uint32_t bufOff = (uint32_t)stComp * STAGE_BYTES;
        if (++stComp == NSTAGE) stComp = 0;

        #pragma unroll
        for (int ks = 0; ks < 2; ++ks) {
            int kb = ks * 16;
            uint32_t aF[4][4], bF[4][2];
            #pragma unroll
            for (int mi = 0; mi < 4; mi++)
                ldsm4(aF[mi][0], aF[mi][1], aF[mi][2], aF[mi][3],
                      aAddr + bufOff + (mi * 16 * SST + kb) * 2);
            ldsm4(bF[0][0], bF[0][1], bF[1][0], bF[1][1], bAddr + bufOff + kb * 2);
            ldsm4(bF[2][0], bF[2][1], bF[3][0], bF[3][1], bAddr + bufOff + (16 * SST + kb) * 2);
            #pragma unroll
            for (int mi = 0; mi < 4; mi++)
                #pragma unroll
                for (int ni = 0; ni < 4; ni++)
                    mma_bf16(acc[mi][ni], aF[mi], bF[ni]);
        }
    }

    #pragma unroll
    for (int mi = 0; mi < 4; mi++) {
        int r0 = rowBase + mWarp + mi * 16 + gr;
        #pragma unroll
        for (int ni = 0; ni < 4; ni++) {
            int c0 = colBase + nWarp + ni * 8 + lc * 2;
            emit_pair<MODE>(r0,     c0, acc[mi][ni][0], acc[mi][ni][1], bias, extra, out);
            emit_pair<MODE>(r0 + 8, c0, acc[mi][ni][2], acc[mi][ni][3], bias, extra, out);
        }
    }
}

// ------------- tensor-core attention: warp = (head, row-half) --------------
#define VST 40
__global__ void __launch_bounds__(256) attn_kernel(const float* __restrict__ rpb)
{
    __shared__ bf16 vs[8][64][VST];

    int blk  = blockIdx.x;
    int win  = blk >> 1, half = blk & 1;
    int tid  = threadIdx.x;
    int lane = tid & 31, head = tid >> 5;
    int gr = lane >> 2, lc = lane & 3;

    size_t hb = ((size_t)win * 8 + head) * 64 * 32;
    const uint32_t* q32 = (const uint32_t*)(g_q + hb);
    const uint32_t* k32 = (const uint32_t*)(g_k + hb);

    {
        const bf16* vsrc = g_v + hb;
        #pragma unroll
        for (int it = 0; it < 8; it++) {
            int c = it * 32 + lane;
            int row = c >> 2, k8 = (c & 3) * 8;
            cp_async16(&vs[head][row][k8], vsrc + row * 32 + k8);
        }
        cp_commit();
    }

    float sacc[2][8][4];
    #pragma unroll
    for (int mt = 0; mt < 2; mt++)
        #pragma unroll
        for (int nt = 0; nt < 8; nt++)
            #pragma unroll
            for (int e = 0; e < 4; e++) sacc[mt][nt][e] = 0.f;

    #pragma unroll
    for (int kt = 0; kt < 2; kt++) {
        uint32_t aQ[2][4];
        #pragma unroll
        for (int mt = 0; mt < 2; mt++) {
            int i0 = half * 32 + mt * 16 + gr;
            aQ[mt][0] = q32[i0 * 16 + 8 * kt + lc];
            aQ[mt][1] = q32[(i0 + 8) * 16 + 8 * kt + lc];
            aQ[mt][2] = q32[i0 * 16 + 8 * kt + lc + 4];
            aQ[mt][3] = q32[(i0 + 8) * 16 + 8 * kt + lc + 4];
        }
        uint32_t bK[8][2];
        #pragma unroll
        for (int nt = 0; nt < 8; nt++) {
            int j0 = nt * 8 + gr;
            bK[nt][0] = k32[j0 * 16 + 8 * kt + lc];
            bK[nt][1] = k32[j0 * 16 + 8 * kt + lc + 4];
        }
        #pragma unroll
        for (int mt = 0; mt < 2; mt++)
            #pragma unroll
            for (int nt = 0; nt < 8; nt++)
                mma_bf16(sacc[mt][nt], aQ[mt], bK[nt]);
    }

    int nw  = win & 63;
    int whb = (nw >> 3) * WSZ, wwb = (nw & 7) * WSZ;
    #pragma unroll
    for (int mt = 0; mt < 2; mt++) {
        #pragma unroll
        for (int re = 0; re < 2; re++) {
            int i = half * 32 + mt * 16 + gr + 8 * re;
            int ri = i >> 3, ci = i & 7;
            int yi = whb + ri, xi = wwb + ci;
            int labi = (yi < 56 ? 0 : (yi < 60 ? 1 : 2)) * 3 + (xi < 56 ? 0 : (xi < 60 ? 1 : 2));
            #pragma unroll
            for (int nt = 0; nt < 8; nt++) {
                #pragma unroll
                for (int e2 = 0; e2 < 2; e2++) {
                    int j = nt * 8 + 2 * lc + e2;
                    int rj = j >> 3, cj = j & 7;
                    int rel = (ri - rj + 7) * 15 + (ci - cj + 7);
                    float a = __ldg(&rpb[rel * 8 + head]);
                    int yj = whb + rj, xj = wwb + cj;
                    int labj = (yj < 56 ? 0 : (yj < 60 ? 1 : 2)) * 3 + (xj < 56 ? 0 : (xj < 60 ? 1 : 2));
                    if (labj != labi) a -= 100.f;
                    sacc[mt][nt][re * 2 + e2] += a;
                }
            }
        }
    }

    float inv[2][2];
    #pragma unroll
    for (int mt = 0; mt < 2; mt++) {
        #pragma unroll
        for (int re = 0; re < 2; re++) {
            float mx = -1e30f;
            #pragma unroll
            for (int nt = 0; nt < 8; nt++) {
                mx = fmaxf(mx, sacc[mt][nt][re * 2]);
                mx = fmaxf(mx, sacc[mt][nt][re * 2 + 1]);
            }
            mx = fmaxf(mx, __shfl_xor_sync(0xffffffffu, mx, 1));
            mx = fmaxf(mx, __shfl_xor_sync(0xffffffffu, mx, 2));
            float sm = 0.f;
            #pragma unroll
            for (int nt = 0; nt < 8; nt++) {
                float e0 = __expf(sacc[mt][nt][re * 2]     - mx);
                float e1 = __expf(sacc[mt][nt][re * 2 + 1] - mx);
                sacc[mt][nt][re * 2]     = e0;
                sacc[mt][nt][re * 2 + 1] = e1;
                sm += e0 + e1;
            }
            sm += __shfl_xor_sync(0xffffffffu, sm, 1);
            sm += __shfl_xor_sync(0xffffffffu, sm, 2);
            inv[mt][re] = 1.f / sm;
        }
    }

    cp_wait0();
    __syncwarp();

    uint32_t V0 = (uint32_t)__cvta_generic_to_shared(&vs[head][0][0]);
    int vmm = lane >> 3, vr8 = lane & 7;
    int vRow = (vmm & 1) * 8 + vr8, vNd = vmm >> 1;

    float oacc[2][4][4];
    #pragma unroll
    for (int mt = 0; mt < 2; mt++)
        #pragma unroll
        for (int nt = 0; nt < 4; nt++)
            #pragma unroll
            for (int e = 0; e < 4; e++) oacc[mt][nt][e] = 0.f;

    #pragma unroll
    for (int kt = 0; kt < 4; kt++) {
        uint32_t aP[2][4];
        #pragma unroll
        for (int mt = 0; mt < 2; mt++) {
            aP[mt][0] = pack_bf16(sacc[mt][2 * kt][0],     sacc[mt][2 * kt][1]);
            aP[mt][1] = pack_bf16(sacc[mt][2 * kt][2],     sacc[mt][2 * kt][3]);
            aP[mt][2] = pack_bf16(sacc[mt][2 * kt + 1][0], sacc[mt][2 * kt + 1][1]);
            aP[mt][3] = pack_bf16(sacc[mt][2 * kt + 1][2], sacc[mt][2 * kt + 1][3]);
        }
        uint32_t bV[4][2];
        #pragma unroll
        for (int p = 0; p < 2; p++) {
            uint32_t addr = V0 + (((16 * kt + vRow) * VST) + (p * 2 + vNd) * 8) * 2;
            ldsm4t(bV[2*p][0], bV[2*p][1], bV[2*p+1][0], bV[2*p+1][1], addr);
        }
        #pragma unroll
        for (int mt = 0; mt < 2; mt++)
            #pragma unroll
            for (int nt = 0; nt < 4; nt++)
                mma_bf16(oacc[mt][nt], aP[mt], bV[nt]);
    }

    uint32_t* ao32 = (uint32_t*)g_ao;
    #pragma unroll
    for (int mt = 0; mt < 2; mt++) {
        int i0 = half * 32 + mt * 16 + gr;
        float v0 = inv[mt][0], v1 = inv[mt][1];
        #pragma unroll
        for (int nt = 0; nt < 4; nt++) {
            uint32_t p0 = pack_bf16(oacc[mt][nt][0] * v0, oacc[mt][nt][1] * v0);
            uint32_t p1 = pack_bf16(oacc[mt][nt][2] * v1, oacc[mt][nt][3] * v1);
            size_t c = (size_t)head * 16 + nt * 4 + lc;
            ao32[((size_t)win * 64 + i0) * 128 + c]     = p0;
            ao32[((size_t)win * 64 + i0 + 8) * 128 + c] = p1;
        }
    }
}

// ------------------------------- launcher ----------------------------------
extern "C" void kernel_launch(void* const* d_in, const int* in_sizes, int n_in,
                              void* d_out, int out_size)
{
    const float* x0   = (const float*)d_in[0];
    const float* x1   = (const float*)d_in[1];
    const float* g1_0 = (const float*)d_in[2];
    const float* b1_0 = (const float*)d_in[3];
    const float* g1_1 = (const float*)d_in[4];
    const float* b1_1 = (const float*)d_in[5];
    const float* Wq   = (const float*)d_in[6];
    const float* bq   = (const float*)d_in[7];
    const float* Wkv  = (const float*)d_in[8];
    const float* bkv  = (const float*)d_in[9];
    const float* rpb  = (const float*)d_in[10];
    const float* Wp   = (const float*)d_in[11];
    const float* bp   = (const float*)d_in[12];
    const float* g2   = (const float*)d_in[13];
    const float* b2   = (const float*)d_in[14];
    const float* Wfc1 = (const float*)d_in[15];
    const float* bfc1 = (const float*)d_in[16];
    const float* Wfc2 = (const float*)d_in[17];
    const float* bfc2 = (const float*)d_in[18];
    float* out = (float*)d_out;

    bf16 *bWq, *bWkv, *bWp, *bW1, *bW2;
    cudaGetSymbolAddress((void**)&bWq,  g_bWq);
    cudaGetSymbolAddress((void**)&bWkv, g_bWkv);
    cudaGetSymbolAddress((void**)&bWp,  g_bWp);
    cudaGetSymbolAddress((void**)&bW1,  g_bW1);
    cudaGetSymbolAddress((void**)&bW2,  g_bW2);

    cudaFuncSetAttribute(mma_gemm<0>, cudaFuncAttributeMaxDynamicSharedMemorySize, GEMM_SMEM);
    cudaFuncSetAttribute(mma_gemm<1>, cudaFuncAttributeMaxDynamicSharedMemorySize, GEMM_SMEM);
    cudaFuncSetAttribute(mma_gemm<2>, cudaFuncAttributeMaxDynamicSharedMemorySize, GEMM_SMEM);
    cudaFuncSetAttribute(mma_gemm<3>, cudaFuncAttributeMaxDynamicSharedMemorySize, GEMM_SMEM);
    cudaFuncSetAttribute(mma_gemm<4>, cudaFuncAttributeMaxDynamicSharedMemorySize, GEMM_SMEM);

    convert_weights<<<dim3(128, 5), 256>>>(Wq, Wkv, Wp, Wfc1, Wfc2);
    ln_shift_part<<<dim3(MTOK / 8, 2), 256>>>(x0, x1, g1_0, b1_0, g1_1, b1_1);
    mma_gemm<0><<<dim3(2, 512), 256, GEMM_SMEM>>>(bWq,  bq,   256,  nullptr, nullptr);
    mma_gemm<1><<<dim3(4, 512), 256, GEMM_SMEM>>>(bWkv, bkv,  256,  nullptr, nullptr);
    attn_kernel<<<2048, 256>>>(rpb);
    mma_gemm<2><<<dim3(2, 512), 256, GEMM_SMEM>>>(bWp,  bp,   256,  x1,      nullptr);
    ln_plain<<<MTOK / 8, 256>>>(g2, b2);
    mma_gemm<3><<<dim3(8, 512), 256, GEMM_SMEM>>>(bW1,  bfc1, 256,  nullptr, nullptr);
    mma_gemm<4><<<dim3(2, 512), 256, GEMM_SMEM>>>(bW2,  bfc2, 1024, nullptr, out);
}